// round 8
// baseline (speedup 1.0000x reference)
#include <cuda_runtime.h>

// Problem constants: B=16, S=1024, D=256, H=16, DK=16
#define NB 16
#define NS 1024
#define ND 256
#define NH 16
#define NDK 16

// Scratch for projected q,k,v: [B, S, 256] row-major (head h occupies cols h*16..h*16+15)
__device__ float g_q[NB * NS * ND];
__device__ float g_k[NB * NS * ND];
__device__ float g_v[NB * NS * ND];

// ---------------------------------------------------------------------------
// Packed dual-fp32 helpers (Blackwell f32x2).
// ---------------------------------------------------------------------------
typedef unsigned long long ull;

static __device__ __forceinline__ ull pack2(float lo, float hi) {
    ull r;
    asm("mov.b64 %0, {%1, %2};" : "=l"(r) : "f"(lo), "f"(hi));
    return r;
}
static __device__ __forceinline__ void unpack2(ull p, float& lo, float& hi) {
    asm("mov.b64 {%0, %1}, %2;" : "=f"(lo), "=f"(hi) : "l"(p));
}
static __device__ __forceinline__ ull fma2(ull a, ull b, ull c) {
    ull d;
    asm("fma.rn.f32x2 %0, %1, %2, %3;" : "=l"(d) : "l"(a), "l"(b), "l"(c));
    return d;
}
static __device__ __forceinline__ ull add2(ull a, ull b) {
    ull d;
    asm("add.rn.f32x2 %0, %1, %2;" : "=l"(d) : "l"(a), "l"(b));
    return d;
}
static __device__ __forceinline__ ull d2ll(double d) {
    return __double_as_longlong(d);
}

// Fast exp on the fma/alu pipes (no MUFU). Input is already x*log2(e).
static __device__ __forceinline__ float fast_exp(float t) {
    float mm = t + 12582912.0f;             // round-to-nearest (magic 2^23+2^22)
    int   ik = __float_as_int(mm);
    float n  = mm - 12582912.0f;
    float f  = t - n;                        // f in [-0.5, 0.5]
    float f2 = f * f;
    float pA = fmaf(1.33335581464e-3f, f, 9.61812910763e-3f);
    float pB = fmaf(5.55041086648e-2f, f, 2.40226506959e-1f);
    float pC = fmaf(6.93147180560e-1f, f, 1.0f);
    float p  = fmaf(fmaf(pA, f2, pB), f2, pC);
    return __int_as_float(__float_as_int(p) + ((ik - 0x4B400000) << 23));
}

// ---------------------------------------------------------------------------
// Projection GEMM: C[16384,256] = X[16384,256] @ W[256,256] (+bias)
// ---------------------------------------------------------------------------
__global__ __launch_bounds__(256, 2) void proj_kernel(
    const float* __restrict__ Qin, const float* __restrict__ Kin, const float* __restrict__ Vin,
    const float* __restrict__ Wq, const float* __restrict__ bq,
    const float* __restrict__ Wk, const float* __restrict__ Wv, const float* __restrict__ bv)
{
    __shared__ float As[128][17];
    __shared__ float Bs[16][128];

    const int z = blockIdx.z;
    const float* X    = (z == 0) ? Qin : ((z == 1) ? Kin : Vin);
    const float* W    = (z == 0) ? Wq  : ((z == 1) ? Wk  : Wv);
    const float* bias = (z == 0) ? bq  : ((z == 2) ? bv  : (const float*)0);
    float* C          = (z == 0) ? g_q : ((z == 1) ? g_k : g_v);

    const int m0 = blockIdx.y * 128;
    const int n0 = blockIdx.x * 128;
    const int tid = threadIdx.x;
    const int tx = tid & 15;
    const int ty = tid >> 4;

    ull accp[8][4];
#pragma unroll
    for (int i = 0; i < 8; i++)
#pragma unroll
        for (int j = 0; j < 4; j++) accp[i][j] = 0ULL;

    for (int kk = 0; kk < 256; kk += 16) {
#pragma unroll
        for (int i = 0; i < 8; i++) {
            int r = (tid >> 4) + i * 16;
            int c = tid & 15;
            As[r][c] = X[(size_t)(m0 + r) * 256 + kk + c];
        }
#pragma unroll
        for (int i = 0; i < 8; i++) {
            int kr = (tid >> 7) + i * 2;
            int n  = tid & 127;
            Bs[kr][n] = W[(size_t)(kk + kr) * 256 + n0 + n];
        }
        __syncthreads();

#pragma unroll
        for (int k = 0; k < 16; k++) {
            const double2* brow = (const double2*)&Bs[k][tx * 8];
            double2 b0 = brow[0], b1 = brow[1];
            ull bp[4] = { d2ll(b0.x), d2ll(b0.y), d2ll(b1.x), d2ll(b1.y) };
#pragma unroll
            for (int i = 0; i < 8; i++) {
                float a = As[ty * 8 + i][k];
                ull a2 = pack2(a, a);
#pragma unroll
                for (int j = 0; j < 4; j++)
                    accp[i][j] = fma2(a2, bp[j], accp[i][j]);
            }
        }
        __syncthreads();
    }

    float bj[8];
#pragma unroll
    for (int j = 0; j < 8; j++)
        bj[j] = bias ? bias[n0 + tx * 8 + j] : 0.f;

#pragma unroll
    for (int i = 0; i < 8; i++) {
        int m = m0 + ty * 8 + i;
        float v[8];
#pragma unroll
        for (int j = 0; j < 4; j++) unpack2(accp[i][j], v[2 * j], v[2 * j + 1]);
        float4 o0, o1;
        o0.x = v[0] + bj[0]; o0.y = v[1] + bj[1];
        o0.z = v[2] + bj[2]; o0.w = v[3] + bj[3];
        o1.x = v[4] + bj[4]; o1.y = v[5] + bj[5];
        o1.z = v[6] + bj[6]; o1.w = v[7] + bj[7];
        *(float4*)&C[(size_t)m * 256 + n0 + tx * 8]     = o0;
        *(float4*)&C[(size_t)m * 256 + n0 + tx * 8 + 4] = o1;
    }
}

// ---------------------------------------------------------------------------
// Fused attention, LOW-REGISTER variant (~85 regs) so ptxas can software-
// pipeline the LDS->FMA chains. Each warp's 4 rows are processed as TWO
// 2-row sub-passes in both phases. Score tile stored as row-PAIRS
// scp[pg][j][2] (STS.64 / LDS.64, 8B lane stride, conflict-free).
// Warp w: rows rg=(w&7)*4, column half w>>3. 512 threads, 1 CTA/SM.
// ---------------------------------------------------------------------------
#define SC_OFF    0         // 16 pairgroups * 1024 * 2 = 32768 floats
#define KV_OFF    32768     // 1024*20 = 20480
#define QS_OFF    53248     // 512
#define MSK_OFF   53760     // 1024
#define RSUM_OFF  54784     // 32
#define RSP_OFF   54816     // 64
#define CPART_OFF 54880     // 1024
#define ATTN_SMEM_FLOATS 55904
#define ATTN_SMEM_BYTES (ATTN_SMEM_FLOATS * 4)

// One 2-row score sub-pass: rows (row_a, row_a+1), columns half*512..+511.
static __device__ __forceinline__ void score_pass(
    const float* __restrict__ kv, const float* __restrict__ msk,
    const float* __restrict__ qs, float* __restrict__ scp,
    int row_a, int pg, int half, int lane, float& rs_a, float& rs_b)
{
    // q rows -> packed pairs (broadcast LDS, warp-uniform)
    ull qa[8], qb[8];
    {
        const double2* qra = (const double2*)&qs[row_a * 16];
        const double2* qrb = (const double2*)&qs[(row_a + 1) * 16];
#pragma unroll
        for (int c = 0; c < 4; c++) {
            double2 ta = qra[c], tb = qrb[c];
            qa[2 * c] = d2ll(ta.x); qa[2 * c + 1] = d2ll(ta.y);
            qb[2 * c] = d2ll(tb.x); qb[2 * c + 1] = d2ll(tb.y);
        }
    }
    const float C_L2E4 = 0.36067376022224085f;   // log2(e)/4
    float ra = 0.f, rb = 0.f;
#pragma unroll 4
    for (int it = 0; it < 16; it++) {
        const int j = half * 512 + it * 32 + lane;
        const double2* krow = (const double2*)&kv[j * 20];
        double2 k0 = krow[0], k1 = krow[1], k2 = krow[2], k3 = krow[3];
        const float m = msk[j];
        ull kp[8] = { d2ll(k0.x), d2ll(k0.y), d2ll(k1.x), d2ll(k1.y),
                      d2ll(k2.x), d2ll(k2.y), d2ll(k3.x), d2ll(k3.y) };
        // row a dot (two 4-chains)
        ull sa0 = fma2(qa[0], kp[0], 0ULL), sa1 = fma2(qa[4], kp[4], 0ULL);
        sa0 = fma2(qa[1], kp[1], sa0); sa1 = fma2(qa[5], kp[5], sa1);
        sa0 = fma2(qa[2], kp[2], sa0); sa1 = fma2(qa[6], kp[6], sa1);
        sa0 = fma2(qa[3], kp[3], sa0); sa1 = fma2(qa[7], kp[7], sa1);
        // row b dot
        ull sb0 = fma2(qb[0], kp[0], 0ULL), sb1 = fma2(qb[4], kp[4], 0ULL);
        sb0 = fma2(qb[1], kp[1], sb0); sb1 = fma2(qb[5], kp[5], sb1);
        sb0 = fma2(qb[2], kp[2], sb0); sb1 = fma2(qb[6], kp[6], sb1);
        sb0 = fma2(qb[3], kp[3], sb0); sb1 = fma2(qb[7], kp[7], sb1);
        ull s2a = add2(sa0, sa1), s2b = add2(sb0, sb1);
        float alo, ahi, blo, bhi;
        unpack2(s2a, alo, ahi);
        unpack2(s2b, blo, bhi);
        float ea = fast_exp((alo + ahi) * C_L2E4) * m;
        float eb = fast_exp((blo + bhi) * C_L2E4) * m;
        ra += ea; rb += eb;
        *(float2*)&scp[(size_t)(pg * 1024 + j) * 2] = make_float2(ea, eb);  // STS.64
    }
    rs_a = ra; rs_b = rb;
}

// One 2-row context sub-pass: rows (row_a, row_a+1) of this q-tile.
static __device__ __forceinline__ void ctx_pass(
    const float* __restrict__ kv, const float* __restrict__ scp,
    float* __restrict__ aw, float inv_a, float inv_b,
    int row_a, int pg, int half, int lane, ull* acc /*[16]*/)
{
#pragma unroll
    for (int c = 0; c < 16; c++) acc[c] = 0ULL;
#pragma unroll 4
    for (int it = 0; it < 16; it++) {
        const int j = half * 512 + it * 32 + lane;
        const double2* vrow = (const double2*)&kv[j * 20];
        double2 v0 = vrow[0], v1 = vrow[1], v2 = vrow[2], v3 = vrow[3];
        ull vp[8] = { d2ll(v0.x), d2ll(v0.y), d2ll(v1.x), d2ll(v1.y),
                      d2ll(v2.x), d2ll(v2.y), d2ll(v3.x), d2ll(v3.y) };
        float2 e = *(const float2*)&scp[(size_t)(pg * 1024 + j) * 2];       // LDS.64
        __stcs(aw + (size_t)row_a * NS + j,       e.x * inv_a);
        __stcs(aw + (size_t)(row_a + 1) * NS + j, e.y * inv_b);
        ull ea = pack2(e.x, e.x), eb = pack2(e.y, e.y);
#pragma unroll
        for (int c = 0; c < 8; c++) {
            acc[c]     = fma2(ea, vp[c], acc[c]);
            acc[8 + c] = fma2(eb, vp[c], acc[8 + c]);
        }
    }
}

__global__ __launch_bounds__(512, 1) void attn_kernel(
    const int* __restrict__ maskg, float* __restrict__ outg, float* __restrict__ attnw)
{
    extern __shared__ float sm[];
    float* scp   = sm + SC_OFF;
    float* kv    = sm + KV_OFF;
    float* qs    = sm + QS_OFF;
    float* msk   = sm + MSK_OFF;
    float* rsum  = sm + RSUM_OFF;
    float* rsp   = sm + RSP_OFF;
    float* cpart = sm + CPART_OFF;

    const int qt = blockIdx.x, h = blockIdx.y, b = blockIdx.z;
    const int tid  = threadIdx.x;
    const int lane = tid & 31;
    const int w    = tid >> 5;        // 0..15
    const int g    = w & 7;           // row group (rows 4g..4g+3)
    const int rg   = g * 4;
    const int half = w >> 3;          // column half
    const int q0   = qt * 32;

    // --- stage q tile (32x16), mask (1024), K head tile (1024x16) ---
    {
        int r = tid >> 4, d = tid & 15;
        qs[tid] = g_q[(size_t)(b * NS + q0 + r) * ND + h * NDK + d];
    }
    msk[tid]       = (float)maskg[b * NS + tid];
    msk[tid + 512] = (float)maskg[b * NS + tid + 512];
    {
        const float* kbase = g_k + (size_t)b * NS * ND + h * NDK;
#pragma unroll
        for (int i = 0; i < 8; i++) {
            int idx = tid + i * 512;
            int j = idx >> 2, c = idx & 3;
            float4 t = *(const float4*)(kbase + (size_t)j * ND + c * 4);
            *(float4*)&kv[j * 20 + c * 4] = t;
        }
    }
    __syncthreads();

    // --- Phase 1: two 2-row score sub-passes ---
    {
        float r0, r1, r2, r3;
        score_pass(kv, msk, qs, scp, rg,     g * 2,     half, lane, r0, r1);
        score_pass(kv, msk, qs, scp, rg + 2, g * 2 + 1, half, lane, r2, r3);
        // lane reduction
#pragma unroll
        for (int o = 16; o > 0; o >>= 1) {
            r0 += __shfl_xor_sync(0xffffffffu, r0, o);
            r1 += __shfl_xor_sync(0xffffffffu, r1, o);
            r2 += __shfl_xor_sync(0xffffffffu, r2, o);
            r3 += __shfl_xor_sync(0xffffffffu, r3, o);
        }
        if (lane == 0) {
            rsp[w * 4 + 0] = r0; rsp[w * 4 + 1] = r1;
            rsp[w * 4 + 2] = r2; rsp[w * 4 + 3] = r3;
        }
    }
    __syncthreads();
    if (tid < 32) rsum[tid] = 1.0f / (rsp[tid] + rsp[tid + 32] + 1e-8f);
    __syncthreads();

    // --- stage V over kv (K no longer needed) ---
    {
        const float* vbase = g_v + (size_t)b * NS * ND + h * NDK;
#pragma unroll
        for (int i = 0; i < 8; i++) {
            int idx = tid + i * 512;
            int j = idx >> 2, c = idx & 3;
            float4 t = *(const float4*)(vbase + (size_t)j * ND + c * 4);
            *(float4*)&kv[j * 20 + c * 4] = t;
        }
    }
    __syncthreads();

    // --- Phase 3: two 2-row context sub-passes (attn_w stores folded in) ---
    float* aw = attnw + ((size_t)(b * NH + h) * NS + q0) * NS;
    {
        ull acc[16];
        // sub-pass 0: rows rg, rg+1
        ctx_pass(kv, scp, aw, rsum[rg], rsum[rg + 1], rg, g * 2, half, lane, acc);
#pragma unroll
        for (int o = 16; o > 0; o >>= 1)
#pragma unroll
            for (int c = 0; c < 16; c++)
                acc[c] = add2(acc[c], __shfl_xor_sync(0xffffffffu, acc[c], o));
        if (lane == 0) {
#pragma unroll
            for (int c = 0; c < 8; c++) {
                float lo, hi;
                unpack2(acc[c], lo, hi);
                cpart[w * 64 + 0 * 16 + 2 * c] = lo;
                cpart[w * 64 + 0 * 16 + 2 * c + 1] = hi;
                unpack2(acc[8 + c], lo, hi);
                cpart[w * 64 + 1 * 16 + 2 * c] = lo;
                cpart[w * 64 + 1 * 16 + 2 * c + 1] = hi;
            }
        }
        // sub-pass 1: rows rg+2, rg+3
        ctx_pass(kv, scp, aw, rsum[rg + 2], rsum[rg + 3], rg + 2, g * 2 + 1, half, lane, acc);
#pragma unroll
        for (int o = 16; o > 0; o >>= 1)
#pragma unroll
            for (int c = 0; c < 16; c++)
                acc[c] = add2(acc[c], __shfl_xor_sync(0xffffffffu, acc[c], o));
        if (lane == 0) {
#pragma unroll
            for (int c = 0; c < 8; c++) {
                float lo, hi;
                unpack2(acc[c], lo, hi);
                cpart[w * 64 + 2 * 16 + 2 * c] = lo;
                cpart[w * 64 + 2 * 16 + 2 * c + 1] = hi;
                unpack2(acc[8 + c], lo, hi);
                cpart[w * 64 + 3 * 16 + 2 * c] = lo;
                cpart[w * 64 + 3 * 16 + 2 * c + 1] = hi;
            }
        }
    }
    __syncthreads();

    // combine the two column-half partials, normalize, write output
    {
        int r = tid >> 4, d = tid & 15;
        int wg = r >> 2, rr = r & 3;
        float v = cpart[wg * 64 + rr * 16 + d] + cpart[(wg + 8) * 64 + rr * 16 + d];
        v *= rsum[r];
        outg[(size_t)(b * NS + q0 + r) * ND + h * NDK + d] = v;
    }
}

// ---------------------------------------------------------------------------
extern "C" void kernel_launch(void* const* d_in, const int* in_sizes, int n_in,
                              void* d_out, int out_size)
{
    const float* Qin  = (const float*)d_in[0];
    const float* Kin  = (const float*)d_in[1];
    const float* Vin  = (const float*)d_in[2];
    const int*   mask = (const int*)d_in[3];
    const float* Wq   = (const float*)d_in[4];
    const float* bq   = (const float*)d_in[5];
    const float* Wk   = (const float*)d_in[6];
    const float* Wv   = (const float*)d_in[7];
    const float* bv   = (const float*)d_in[8];

    float* out   = (float*)d_out;
    float* attnw = out + (size_t)NB * NS * ND;

    dim3 pg(2, 128, 3);
    proj_kernel<<<pg, 256>>>(Qin, Kin, Vin, Wq, bq, Wk, Wv, bv);

    cudaFuncSetAttribute(attn_kernel, cudaFuncAttributeMaxDynamicSharedMemorySize,
                         ATTN_SMEM_BYTES);
    dim3 ag(NS / 32, NH, NB);
    attn_kernel<<<ag, 512, ATTN_SMEM_BYTES>>>(mask, out, attnw);
}

// round 9
// speedup vs baseline: 1.0932x; 1.0932x over previous
#include <cuda_runtime.h>

// Problem constants: B=16, S=1024, D=256, H=16, DK=16
#define NB 16
#define NS 1024
#define ND 256
#define NH 16
#define NDK 16

// Projected q,k,v in HEAD-CONTIGUOUS layout: [b][h][s][16]
__device__ float g_q[NB * NS * ND];
__device__ float g_k[NB * NS * ND];
__device__ float g_v[NB * NS * ND];

// ---------------------------------------------------------------------------
// Packed dual-fp32 helpers (Blackwell f32x2).
// ---------------------------------------------------------------------------
typedef unsigned long long ull;

static __device__ __forceinline__ ull pack2(float lo, float hi) {
    ull r;
    asm("mov.b64 %0, {%1, %2};" : "=l"(r) : "f"(lo), "f"(hi));
    return r;
}
static __device__ __forceinline__ void unpack2(ull p, float& lo, float& hi) {
    asm("mov.b64 {%0, %1}, %2;" : "=f"(lo), "=f"(hi) : "l"(p));
}
static __device__ __forceinline__ ull fma2(ull a, ull b, ull c) {
    ull d;
    asm("fma.rn.f32x2 %0, %1, %2, %3;" : "=l"(d) : "l"(a), "l"(b), "l"(c));
    return d;
}
static __device__ __forceinline__ ull add2(ull a, ull b) {
    ull d;
    asm("add.rn.f32x2 %0, %1, %2;" : "=l"(d) : "l"(a), "l"(b));
    return d;
}
static __device__ __forceinline__ ull d2ll(double d) {
    return __double_as_longlong(d);
}

// Fast exp on the fma/alu pipes (no MUFU). Input is already x*log2(e).
static __device__ __forceinline__ float fast_exp(float t) {
    float mm = t + 12582912.0f;             // round-to-nearest (magic 2^23+2^22)
    int   ik = __float_as_int(mm);
    float n  = mm - 12582912.0f;
    float f  = t - n;                        // f in [-0.5, 0.5]
    float f2 = f * f;
    float pA = fmaf(1.33335581464e-3f, f, 9.61812910763e-3f);
    float pB = fmaf(5.55041086648e-2f, f, 2.40226506959e-1f);
    float pC = fmaf(6.93147180560e-1f, f, 1.0f);
    float p  = fmaf(fmaf(pA, f2, pB), f2, pC);
    return __int_as_float(__float_as_int(p) + ((ik - 0x4B400000) << 23));
}

// ---------------------------------------------------------------------------
// Projection GEMM: C = X[16384,256] @ W[256,256] (+bias), output re-laid-out
// to head-contiguous [b][h][s][16].
// ---------------------------------------------------------------------------
__global__ __launch_bounds__(256, 2) void proj_kernel(
    const float* __restrict__ Qin, const float* __restrict__ Kin, const float* __restrict__ Vin,
    const float* __restrict__ Wq, const float* __restrict__ bq,
    const float* __restrict__ Wk, const float* __restrict__ Wv, const float* __restrict__ bv)
{
    __shared__ float As[128][17];
    __shared__ float Bs[16][128];

    const int z = blockIdx.z;
    const float* X    = (z == 0) ? Qin : ((z == 1) ? Kin : Vin);
    const float* W    = (z == 0) ? Wq  : ((z == 1) ? Wk  : Wv);
    const float* bias = (z == 0) ? bq  : ((z == 2) ? bv  : (const float*)0);
    float* C          = (z == 0) ? g_q : ((z == 1) ? g_k : g_v);

    const int m0 = blockIdx.y * 128;
    const int n0 = blockIdx.x * 128;
    const int tid = threadIdx.x;
    const int tx = tid & 15;
    const int ty = tid >> 4;

    ull accp[8][4];
#pragma unroll
    for (int i = 0; i < 8; i++)
#pragma unroll
        for (int j = 0; j < 4; j++) accp[i][j] = 0ULL;

    for (int kk = 0; kk < 256; kk += 16) {
#pragma unroll
        for (int i = 0; i < 8; i++) {
            int r = (tid >> 4) + i * 16;
            int c = tid & 15;
            As[r][c] = X[(size_t)(m0 + r) * 256 + kk + c];
        }
#pragma unroll
        for (int i = 0; i < 8; i++) {
            int kr = (tid >> 7) + i * 2;
            int n  = tid & 127;
            Bs[kr][n] = W[(size_t)(kk + kr) * 256 + n0 + n];
        }
        __syncthreads();

#pragma unroll
        for (int k = 0; k < 16; k++) {
            const double2* brow = (const double2*)&Bs[k][tx * 8];
            double2 b0 = brow[0], b1 = brow[1];
            ull bp[4] = { d2ll(b0.x), d2ll(b0.y), d2ll(b1.x), d2ll(b1.y) };
#pragma unroll
            for (int i = 0; i < 8; i++) {
                float a = As[ty * 8 + i][k];
                ull a2 = pack2(a, a);
#pragma unroll
                for (int j = 0; j < 4; j++)
                    accp[i][j] = fma2(a2, bp[j], accp[i][j]);
            }
        }
        __syncthreads();
    }

    float bj[8];
#pragma unroll
    for (int j = 0; j < 8; j++)
        bj[j] = bias ? bias[n0 + tx * 8 + j] : 0.f;

    // head-contiguous store: thread's 8-col chunk lies inside one head
    const int hh  = (n0 + tx * 8) >> 4;
    const int dk0 = (tx * 8) & 15;     // 0 or 8
#pragma unroll
    for (int i = 0; i < 8; i++) {
        int m = m0 + ty * 8 + i;
        int bb = m >> 10, s = m & 1023;
        float v[8];
#pragma unroll
        for (int j = 0; j < 4; j++) unpack2(accp[i][j], v[2 * j], v[2 * j + 1]);
        float4 o0, o1;
        o0.x = v[0] + bj[0]; o0.y = v[1] + bj[1];
        o0.z = v[2] + bj[2]; o0.w = v[3] + bj[3];
        o1.x = v[4] + bj[4]; o1.y = v[5] + bj[5];
        o1.z = v[6] + bj[6]; o1.w = v[7] + bj[7];
        float* dst = &C[((size_t)(bb * NH + hh) * NS + s) * NDK + dk0];
        *(float4*)dst       = o0;
        *(float4*)(dst + 4) = o1;
    }
}

// ---------------------------------------------------------------------------
// Fused attention, FULLY DECOUPLED WARPS. One block per (b, h, 32-row q tile),
// 512 threads = 16 warps; warp w owns rows 2w, 2w+1 over ALL 1024 columns.
// K and V both staged in smem up front (one __syncthreads); scores live in
// registers (ev[2][32]); rowsum + context reductions are lane shuffles only.
// NO barriers after staging — warps free-run.
// ---------------------------------------------------------------------------
#define KVK_OFF  0          // 1024*20 = 20480 floats
#define KVV_OFF  20480      // 20480
#define QS_OFF   40960      // 512
#define MSK_OFF  41472      // 1024
#define ATTN_SMEM_FLOATS 42496
#define ATTN_SMEM_BYTES (ATTN_SMEM_FLOATS * 4)

__global__ __launch_bounds__(512, 1) void attn_kernel(
    const int* __restrict__ maskg, float* __restrict__ outg, float* __restrict__ attnw)
{
    extern __shared__ float sm[];
    float* kvK = sm + KVK_OFF;
    float* kvV = sm + KVV_OFF;
    float* qs  = sm + QS_OFF;
    float* msk = sm + MSK_OFF;

    const int qt = blockIdx.x, h = blockIdx.y, b = blockIdx.z;
    const int tid  = threadIdx.x;
    const int lane = tid & 31;
    const int w    = tid >> 5;        // 0..15; owns rows 2w, 2w+1
    const int q0   = qt * 32;

    // --- stage q (32x16 contiguous), mask, K tile, V tile; ONE sync ---
    qs[tid] = g_q[((size_t)(b * NH + h) * NS + q0) * NDK + tid];
    msk[tid]       = (float)maskg[b * NS + tid];
    msk[tid + 512] = (float)maskg[b * NS + tid + 512];
    {
        const float4* kb = (const float4*)(g_k + (size_t)(b * NH + h) * NS * NDK);
        const float4* vb = (const float4*)(g_v + (size_t)(b * NH + h) * NS * NDK);
#pragma unroll
        for (int i = 0; i < 8; i++) {
            int idx = tid + i * 512;          // 0..4095
            int j = idx >> 2, c = idx & 3;
            *(float4*)&kvK[j * 20 + c * 4] = kb[idx];
            *(float4*)&kvV[j * 20 + c * 4] = vb[idx];
        }
    }
    __syncthreads();   // the ONLY barrier

    // q rows 2w, 2w+1 -> packed pairs
    ull qp0[8], qp1[8];
    {
        const double2* qa = (const double2*)&qs[(2 * w) * 16];
        const double2* qb = (const double2*)&qs[(2 * w + 1) * 16];
#pragma unroll
        for (int c = 0; c < 4; c++) {
            double2 ta = qa[c], tb = qb[c];
            qp0[2 * c] = d2ll(ta.x); qp0[2 * c + 1] = d2ll(ta.y);
            qp1[2 * c] = d2ll(tb.x); qp1[2 * c + 1] = d2ll(tb.y);
        }
    }

    // --- Pass 1: scores for 2 rows over all 1024 columns; e kept in regs ---
    const float C_L2E4 = 0.36067376022224085f;   // log2(e)/4
    float ev0[32], ev1[32];
    float rs0 = 0.f, rs1 = 0.f;
#pragma unroll
    for (int it = 0; it < 32; it++) {
        const int j = it * 32 + lane;
        const double2* krow = (const double2*)&kvK[j * 20];
        double2 k0 = krow[0], k1 = krow[1], k2 = krow[2], k3 = krow[3];
        const float m = msk[j];
        ull kpa = d2ll(k0.x), kpb = d2ll(k0.y);
        ull s00 = fma2(qp0[0], kpa, 0ULL), s10 = fma2(qp1[0], kpa, 0ULL);
        ull s01 = fma2(qp0[1], kpb, 0ULL), s11 = fma2(qp1[1], kpb, 0ULL);
        kpa = d2ll(k1.x); kpb = d2ll(k1.y);
        s00 = fma2(qp0[2], kpa, s00); s10 = fma2(qp1[2], kpa, s10);
        s01 = fma2(qp0[3], kpb, s01); s11 = fma2(qp1[3], kpb, s11);
        kpa = d2ll(k2.x); kpb = d2ll(k2.y);
        s00 = fma2(qp0[4], kpa, s00); s10 = fma2(qp1[4], kpa, s10);
        s01 = fma2(qp0[5], kpb, s01); s11 = fma2(qp1[5], kpb, s11);
        kpa = d2ll(k3.x); kpb = d2ll(k3.y);
        s00 = fma2(qp0[6], kpa, s00); s10 = fma2(qp1[6], kpa, s10);
        s01 = fma2(qp0[7], kpb, s01); s11 = fma2(qp1[7], kpb, s11);
        ull t0 = add2(s00, s01), t1 = add2(s10, s11);
        float a0, a1, b0, b1;
        unpack2(t0, a0, a1);
        unpack2(t1, b0, b1);
        float e0 = fast_exp((a0 + a1) * C_L2E4) * m;
        float e1 = fast_exp((b0 + b1) * C_L2E4) * m;
        ev0[it] = e0; rs0 += e0;
        ev1[it] = e1; rs1 += e1;
    }
    // lane butterfly: every lane gets the full row sums
#pragma unroll
    for (int o = 16; o > 0; o >>= 1) {
        rs0 += __shfl_xor_sync(0xffffffffu, rs0, o);
        rs1 += __shfl_xor_sync(0xffffffffu, rs1, o);
    }
    const float inv0 = 1.0f / (rs0 + 1e-8f);
    const float inv1 = 1.0f / (rs1 + 1e-8f);

    // --- Pass 2: context + normalized attn_w stores (no barrier needed) ---
    float* aw0 = attnw + ((size_t)(b * NH + h) * NS + q0 + 2 * w) * NS;
    float* aw1 = aw0 + NS;

    ull acc[16];
#pragma unroll
    for (int c = 0; c < 16; c++) acc[c] = 0ULL;

#pragma unroll
    for (int it = 0; it < 32; it++) {
        const int j = it * 32 + lane;
        const double2* vrow = (const double2*)&kvV[j * 20];
        double2 v0 = vrow[0], v1 = vrow[1], v2 = vrow[2], v3 = vrow[3];
        float e0 = ev0[it], e1 = ev1[it];
        __stcs(aw0 + j, e0 * inv0);
        __stcs(aw1 + j, e1 * inv1);
        ull ep0 = pack2(e0, e0), ep1 = pack2(e1, e1);
        ull vp;
        vp = d2ll(v0.x); acc[0] = fma2(ep0, vp, acc[0]); acc[8]  = fma2(ep1, vp, acc[8]);
        vp = d2ll(v0.y); acc[1] = fma2(ep0, vp, acc[1]); acc[9]  = fma2(ep1, vp, acc[9]);
        vp = d2ll(v1.x); acc[2] = fma2(ep0, vp, acc[2]); acc[10] = fma2(ep1, vp, acc[10]);
        vp = d2ll(v1.y); acc[3] = fma2(ep0, vp, acc[3]); acc[11] = fma2(ep1, vp, acc[11]);
        vp = d2ll(v2.x); acc[4] = fma2(ep0, vp, acc[4]); acc[12] = fma2(ep1, vp, acc[12]);
        vp = d2ll(v2.y); acc[5] = fma2(ep0, vp, acc[5]); acc[13] = fma2(ep1, vp, acc[13]);
        vp = d2ll(v3.x); acc[6] = fma2(ep0, vp, acc[6]); acc[14] = fma2(ep1, vp, acc[14]);
        vp = d2ll(v3.y); acc[7] = fma2(ep0, vp, acc[7]); acc[15] = fma2(ep1, vp, acc[15]);
    }

    // lane butterfly on packed accumulators: every lane ends with full sums
#pragma unroll
    for (int o = 16; o > 0; o >>= 1)
#pragma unroll
        for (int c = 0; c < 16; c++)
            acc[c] = add2(acc[c], __shfl_xor_sync(0xffffffffu, acc[c], o));

    // output: lanes 0..15 -> row 2w dims 0..15; lanes 16..31 -> row 2w+1
    {
        const int row = lane >> 4, d = lane & 15;
        float lo, hi;
        unpack2(acc[row * 8 + (d >> 1)], lo, hi);
        float v = ((d & 1) ? hi : lo) * (row ? inv1 : inv0);
        outg[((size_t)(b * NS + q0 + 2 * w + row)) * ND + h * NDK + d] = v;
    }
}

// ---------------------------------------------------------------------------
extern "C" void kernel_launch(void* const* d_in, const int* in_sizes, int n_in,
                              void* d_out, int out_size)
{
    const float* Qin  = (const float*)d_in[0];
    const float* Kin  = (const float*)d_in[1];
    const float* Vin  = (const float*)d_in[2];
    const int*   mask = (const int*)d_in[3];
    const float* Wq   = (const float*)d_in[4];
    const float* bq   = (const float*)d_in[5];
    const float* Wk   = (const float*)d_in[6];
    const float* Wv   = (const float*)d_in[7];
    const float* bv   = (const float*)d_in[8];

    float* out   = (float*)d_out;
    float* attnw = out + (size_t)NB * NS * ND;

    dim3 pg(2, 128, 3);
    proj_kernel<<<pg, 256>>>(Qin, Kin, Vin, Wq, bq, Wk, Wv, bv);

    cudaFuncSetAttribute(attn_kernel, cudaFuncAttributeMaxDynamicSharedMemorySize,
                         ATTN_SMEM_BYTES);
    dim3 ag(NS / 32, NH, NB);
    attn_kernel<<<ag, 512, ATTN_SMEM_BYTES>>>(mask, out, attnw);
}

// round 10
// speedup vs baseline: 1.2385x; 1.1329x over previous
#include <cuda_runtime.h>
#include <cuda_fp16.h>

// Problem constants: B=16, S=1024, D=256, H=16, DK=16
#define NB 16
#define NS 1024
#define ND 256
#define NH 16
#define NDK 16

// Projected tensors, head-contiguous [b][h][s][16].
// q stays fp32 (score accuracy); k,v stored fp16 (crossbar/DRAM halving).
__device__ float  g_q[NB * NS * ND];
__device__ __half g_kh[NB * NS * ND];
__device__ __half g_vh[NB * NS * ND];

// ---------------------------------------------------------------------------
// Packed dual-fp32 helpers (Blackwell f32x2).
// ---------------------------------------------------------------------------
typedef unsigned long long ull;

static __device__ __forceinline__ ull pack2(float lo, float hi) {
    ull r;
    asm("mov.b64 %0, {%1, %2};" : "=l"(r) : "f"(lo), "f"(hi));
    return r;
}
static __device__ __forceinline__ void unpack2(ull p, float& lo, float& hi) {
    asm("mov.b64 {%0, %1}, %2;" : "=f"(lo), "=f"(hi) : "l"(p));
}
static __device__ __forceinline__ ull fma2(ull a, ull b, ull c) {
    ull d;
    asm("fma.rn.f32x2 %0, %1, %2, %3;" : "=l"(d) : "l"(a), "l"(b), "l"(c));
    return d;
}
static __device__ __forceinline__ ull add2(ull a, ull b) {
    ull d;
    asm("add.rn.f32x2 %0, %1, %2;" : "=l"(d) : "l"(a), "l"(b));
    return d;
}
static __device__ __forceinline__ ull d2ll(double d) {
    return __double_as_longlong(d);
}
// half2 bits -> packed float pair
static __device__ __forceinline__ ull h2ll(unsigned int h2bits) {
    __half2 h = *reinterpret_cast<__half2*>(&h2bits);
    float2 f = __half22float2(h);
    return pack2(f.x, f.y);
}

// Fast exp on the fma/alu pipes (no MUFU). Input is already x*log2(e).
static __device__ __forceinline__ float fast_exp(float t) {
    float mm = t + 12582912.0f;             // round-to-nearest (magic 2^23+2^22)
    int   ik = __float_as_int(mm);
    float n  = mm - 12582912.0f;
    float f  = t - n;                        // f in [-0.5, 0.5]
    float f2 = f * f;
    float pA = fmaf(1.33335581464e-3f, f, 9.61812910763e-3f);
    float pB = fmaf(5.55041086648e-2f, f, 2.40226506959e-1f);
    float pC = fmaf(6.93147180560e-1f, f, 1.0f);
    float p  = fmaf(fmaf(pA, f2, pB), f2, pC);
    return __int_as_float(__float_as_int(p) + ((ik - 0x4B400000) << 23));
}

// ---------------------------------------------------------------------------
// Projection GEMM: C = X[16384,256] @ W[256,256] (+bias).
// z=0 -> g_q (fp32); z=1 -> g_kh (fp16); z=2 -> g_vh (fp16).
// Output layout head-contiguous [b][h][s][16].
// ---------------------------------------------------------------------------
__global__ __launch_bounds__(256, 2) void proj_kernel(
    const float* __restrict__ Qin, const float* __restrict__ Kin, const float* __restrict__ Vin,
    const float* __restrict__ Wq, const float* __restrict__ bq,
    const float* __restrict__ Wk, const float* __restrict__ Wv, const float* __restrict__ bv)
{
    __shared__ float As[128][17];
    __shared__ float Bs[16][128];

    const int z = blockIdx.z;
    const float* X    = (z == 0) ? Qin : ((z == 1) ? Kin : Vin);
    const float* W    = (z == 0) ? Wq  : ((z == 1) ? Wk  : Wv);
    const float* bias = (z == 0) ? bq  : ((z == 2) ? bv  : (const float*)0);

    const int m0 = blockIdx.y * 128;
    const int n0 = blockIdx.x * 128;
    const int tid = threadIdx.x;
    const int tx = tid & 15;
    const int ty = tid >> 4;

    ull accp[8][4];
#pragma unroll
    for (int i = 0; i < 8; i++)
#pragma unroll
        for (int j = 0; j < 4; j++) accp[i][j] = 0ULL;

    for (int kk = 0; kk < 256; kk += 16) {
#pragma unroll
        for (int i = 0; i < 8; i++) {
            int r = (tid >> 4) + i * 16;
            int c = tid & 15;
            As[r][c] = X[(size_t)(m0 + r) * 256 + kk + c];
        }
#pragma unroll
        for (int i = 0; i < 8; i++) {
            int kr = (tid >> 7) + i * 2;
            int n  = tid & 127;
            Bs[kr][n] = W[(size_t)(kk + kr) * 256 + n0 + n];
        }
        __syncthreads();

#pragma unroll
        for (int k = 0; k < 16; k++) {
            const double2* brow = (const double2*)&Bs[k][tx * 8];
            double2 b0 = brow[0], b1 = brow[1];
            ull bp[4] = { d2ll(b0.x), d2ll(b0.y), d2ll(b1.x), d2ll(b1.y) };
#pragma unroll
            for (int i = 0; i < 8; i++) {
                float a = As[ty * 8 + i][k];
                ull a2 = pack2(a, a);
#pragma unroll
                for (int j = 0; j < 4; j++)
                    accp[i][j] = fma2(a2, bp[j], accp[i][j]);
            }
        }
        __syncthreads();
    }

    float bj[8];
#pragma unroll
    for (int j = 0; j < 8; j++)
        bj[j] = bias ? bias[n0 + tx * 8 + j] : 0.f;

    const int hh  = (n0 + tx * 8) >> 4;    // head index
    const int dk0 = (tx * 8) & 15;         // 0 or 8 within head
#pragma unroll
    for (int i = 0; i < 8; i++) {
        int m = m0 + ty * 8 + i;
        int bb = m >> 10, s = m & 1023;
        float v[8];
#pragma unroll
        for (int j = 0; j < 4; j++) unpack2(accp[i][j], v[2 * j], v[2 * j + 1]);
#pragma unroll
        for (int j = 0; j < 8; j++) v[j] += bj[j];

        if (z == 0) {
            float* dst = &g_q[((size_t)(bb * NH + hh) * NS + s) * NDK + dk0];
            float4 o0 = make_float4(v[0], v[1], v[2], v[3]);
            float4 o1 = make_float4(v[4], v[5], v[6], v[7]);
            *(float4*)dst       = o0;
            *(float4*)(dst + 4) = o1;
        } else {
            __half2 h0 = __floats2half2_rn(v[0], v[1]);
            __half2 h1 = __floats2half2_rn(v[2], v[3]);
            __half2 h2 = __floats2half2_rn(v[4], v[5]);
            __half2 h3 = __floats2half2_rn(v[6], v[7]);
            uint4 o;
            o.x = *(unsigned int*)&h0; o.y = *(unsigned int*)&h1;
            o.z = *(unsigned int*)&h2; o.w = *(unsigned int*)&h3;
            __half* dst = (z == 1) ? &g_kh[((size_t)(bb * NH + hh) * NS + s) * NDK + dk0]
                                   : &g_vh[((size_t)(bb * NH + hh) * NS + s) * NDK + dk0];
            *(uint4*)dst = o;   // 16B store, dk0 in {0,8} halves -> 0/16B aligned
        }
    }
}

// ---------------------------------------------------------------------------
// Fused attention (R7 structure, fp16 K/V tiles). One block per
// (b, h, 32-row q tile). 512 threads = 16 warps.
// Warp w: row group g=w&7 (rows 4g..4g+3), column half w>>3.
// kv tile: 1024 rows x 24 halves (48B stride; 12-word stride makes the two
// LDS.128 per row hit all 32 banks exactly once across an 8-lane phase).
// Score tile scq[g][j][4] fp32: STS.128 in phase 1, LDS.128 in phase 3.
// ---------------------------------------------------------------------------
#define SC_OFF    0         // 32768 floats
#define KV_OFF    32768     // 1024*24 halves = 12288 floats
#define QS_OFF    45056     // 512
#define MSK_OFF   45568     // 1024
#define RSUM_OFF  46592     // 32
#define RSP_OFF   46624     // 64
#define CPART_OFF 46688     // 1024
#define ATTN_SMEM_FLOATS 47712
#define ATTN_SMEM_BYTES (ATTN_SMEM_FLOATS * 4)

__global__ __launch_bounds__(512, 1) void attn_kernel(
    const int* __restrict__ maskg, float* __restrict__ outg, float* __restrict__ attnw)
{
    extern __shared__ float sm[];
    float*  sc    = sm + SC_OFF;                 // scq[g][j][4]
    __half* kvh   = (__half*)(sm + KV_OFF);      // [1024][24] halves
    float*  qs    = sm + QS_OFF;
    float*  msk   = sm + MSK_OFF;
    float*  rsum  = sm + RSUM_OFF;
    float*  rsp   = sm + RSP_OFF;
    float*  cpart = sm + CPART_OFF;

    const int qt = blockIdx.x, h = blockIdx.y, b = blockIdx.z;
    const int tid  = threadIdx.x;
    const int lane = tid & 31;
    const int w    = tid >> 5;        // 0..15
    const int g    = w & 7;           // row group (rows 4g..4g+3)
    const int rg   = g * 4;
    const int half = w >> 3;          // column half
    const int q0   = qt * 32;

    // --- stage q (32x16 contiguous fp32), mask, K half-tile; ONE sync ---
    qs[tid] = g_q[((size_t)(b * NH + h) * NS + q0) * NDK + tid];
    msk[tid]       = (float)maskg[b * NS + tid];
    msk[tid + 512] = (float)maskg[b * NS + tid + 512];
    {
        const uint4* kb = (const uint4*)(g_kh + (size_t)(b * NH + h) * NS * NDK);
#pragma unroll
        for (int i = 0; i < 4; i++) {
            int idx = tid + i * 512;          // 0..2047 16B-chunks
            int j = idx >> 1, c = idx & 1;
            *(uint4*)(kvh + (size_t)j * 24 + c * 8) = kb[idx];
        }
    }
    __syncthreads();

    // q rows -> packed register pairs over d
    ull qp[4][8];
#pragma unroll
    for (int r = 0; r < 4; r++) {
        const double2* qrow = (const double2*)&qs[(rg + r) * 16];
#pragma unroll
        for (int c = 0; c < 4; c++) {
            double2 t = qrow[c];
            qp[r][2 * c]     = d2ll(t.x);
            qp[r][2 * c + 1] = d2ll(t.y);
        }
    }

    // --- Phase 1: scores; 2 LDS.128 of half K per column, fp32 math ---
    const float C_L2E4 = 0.36067376022224085f;   // log2(e)/4
    float rs[4] = {0.f, 0.f, 0.f, 0.f};
#pragma unroll 1
    for (int it = 0; it < 16; it++) {
        const int j = half * 512 + it * 32 + lane;
        uint4 ka = *(const uint4*)(kvh + (size_t)j * 24);
        uint4 kb = *(const uint4*)(kvh + (size_t)j * 24 + 8);
        ull kp[8];
        kp[0] = h2ll(ka.x); kp[1] = h2ll(ka.y);
        kp[2] = h2ll(ka.z); kp[3] = h2ll(ka.w);
        kp[4] = h2ll(kb.x); kp[5] = h2ll(kb.y);
        kp[6] = h2ll(kb.z); kp[7] = h2ll(kb.w);
        const float m = msk[j];
        float ev[4];
#pragma unroll
        for (int r = 0; r < 4; r++) {
            ull sa = fma2(qp[r][0], kp[0], 0ULL);
            ull sb = fma2(qp[r][4], kp[4], 0ULL);
            sa = fma2(qp[r][1], kp[1], sa);
            sb = fma2(qp[r][5], kp[5], sb);
            sa = fma2(qp[r][2], kp[2], sa);
            sb = fma2(qp[r][6], kp[6], sb);
            sa = fma2(qp[r][3], kp[3], sa);
            sb = fma2(qp[r][7], kp[7], sb);
            ull s2 = add2(sa, sb);
            float slo, shi;
            unpack2(s2, slo, shi);
            ev[r] = fast_exp((slo + shi) * C_L2E4) * m;
            rs[r] += ev[r];
        }
        float4 e4;
        e4.x = ev[0]; e4.y = ev[1]; e4.z = ev[2]; e4.w = ev[3];
        *(float4*)&sc[(size_t)(g * 1024 + j) * 4] = e4;   // STS.128
    }
    // row-sum: reduce across lanes, then across the two column halves
#pragma unroll
    for (int o = 16; o > 0; o >>= 1) {
#pragma unroll
        for (int r = 0; r < 4; r++)
            rs[r] += __shfl_xor_sync(0xffffffffu, rs[r], o);
    }
    if (lane == 0) {
#pragma unroll
        for (int r = 0; r < 4; r++) rsp[w * 4 + r] = rs[r];
    }
    __syncthreads();
    if (tid < 32) rsum[tid] = 1.0f / (rsp[tid] + rsp[tid + 32] + 1e-8f);
    __syncthreads();

    // --- stage V half-tile over kv (K no longer needed) ---
    {
        const uint4* vb = (const uint4*)(g_vh + (size_t)(b * NH + h) * NS * NDK);
#pragma unroll
        for (int i = 0; i < 4; i++) {
            int idx = tid + i * 512;
            int j = idx >> 1, c = idx & 1;
            *(uint4*)(kvh + (size_t)j * 24 + c * 8) = vb[idx];
        }
    }
    __syncthreads();

    // --- Phase 3: context = sc @ v; LDS.128 score quad; attn_w folded in ---
    float inv[4];
#pragma unroll
    for (int r = 0; r < 4; r++) inv[r] = rsum[rg + r];

    float* aw = attnw + ((size_t)(b * NH + h) * NS + q0) * NS;

    ull accp[4][8];
#pragma unroll
    for (int r = 0; r < 4; r++)
#pragma unroll
        for (int c = 0; c < 8; c++) accp[r][c] = 0ULL;

#pragma unroll 1
    for (int it = 0; it < 16; it++) {
        const int j = half * 512 + it * 32 + lane;
        uint4 va = *(const uint4*)(kvh + (size_t)j * 24);
        uint4 vb = *(const uint4*)(kvh + (size_t)j * 24 + 8);
        ull vp[8];
        vp[0] = h2ll(va.x); vp[1] = h2ll(va.y);
        vp[2] = h2ll(va.z); vp[3] = h2ll(va.w);
        vp[4] = h2ll(vb.x); vp[5] = h2ll(vb.y);
        vp[6] = h2ll(vb.z); vp[7] = h2ll(vb.w);
        float4 e4 = *(const float4*)&sc[(size_t)(g * 1024 + j) * 4];  // LDS.128
        __stcs(aw + (size_t)(rg + 0) * NS + j, e4.x * inv[0]);
        __stcs(aw + (size_t)(rg + 1) * NS + j, e4.y * inv[1]);
        __stcs(aw + (size_t)(rg + 2) * NS + j, e4.z * inv[2]);
        __stcs(aw + (size_t)(rg + 3) * NS + j, e4.w * inv[3]);
        ull e0 = pack2(e4.x, e4.x), e1 = pack2(e4.y, e4.y);
        ull e2 = pack2(e4.z, e4.z), e3 = pack2(e4.w, e4.w);
#pragma unroll
        for (int c = 0; c < 8; c++) {
            accp[0][c] = fma2(e0, vp[c], accp[0][c]);
            accp[1][c] = fma2(e1, vp[c], accp[1][c]);
            accp[2][c] = fma2(e2, vp[c], accp[2][c]);
            accp[3][c] = fma2(e3, vp[c], accp[3][c]);
        }
    }

    // lane reduction on packed accumulators
#pragma unroll
    for (int o = 16; o > 0; o >>= 1)
#pragma unroll
        for (int r = 0; r < 4; r++)
#pragma unroll
            for (int c = 0; c < 8; c++)
                accp[r][c] = add2(accp[r][c], __shfl_xor_sync(0xffffffffu, accp[r][c], o));

    if (lane == 0) {
#pragma unroll
        for (int r = 0; r < 4; r++)
#pragma unroll
            for (int c = 0; c < 8; c++) {
                float lo, hi;
                unpack2(accp[r][c], lo, hi);
                cpart[w * 64 + r * 16 + 2 * c]     = lo;
                cpart[w * 64 + r * 16 + 2 * c + 1] = hi;
            }
    }
    __syncthreads();

    // combine the two column-half partials, normalize, write output
    {
        int r = tid >> 4, d = tid & 15;
        int wg = r >> 2, rr = r & 3;
        float v = cpart[wg * 64 + rr * 16 + d] + cpart[(wg + 8) * 64 + rr * 16 + d];
        v *= rsum[r];
        outg[(size_t)(b * NS + q0 + r) * ND + h * NDK + d] = v;
    }
}

// ---------------------------------------------------------------------------
extern "C" void kernel_launch(void* const* d_in, const int* in_sizes, int n_in,
                              void* d_out, int out_size)
{
    const float* Qin  = (const float*)d_in[0];
    const float* Kin  = (const float*)d_in[1];
    const float* Vin  = (const float*)d_in[2];
    const int*   mask = (const int*)d_in[3];
    const float* Wq   = (const float*)d_in[4];
    const float* bq   = (const float*)d_in[5];
    const float* Wk   = (const float*)d_in[6];
    const float* Wv   = (const float*)d_in[7];
    const float* bv   = (const float*)d_in[8];

    float* out   = (float*)d_out;
    float* attnw = out + (size_t)NB * NS * ND;

    dim3 pg(2, 128, 3);
    proj_kernel<<<pg, 256>>>(Qin, Kin, Vin, Wq, bq, Wk, Wv, bv);

    cudaFuncSetAttribute(attn_kernel, cudaFuncAttributeMaxDynamicSharedMemorySize,
                         ATTN_SMEM_BYTES);
    dim3 ag(NS / 32, NH, NB);
    attn_kernel<<<ag, 512, ATTN_SMEM_BYTES>>>(mask, out, attnw);
}

// round 11
// speedup vs baseline: 1.3893x; 1.1218x over previous
#include <cuda_runtime.h>
#include <cuda_fp16.h>

// Problem constants: B=16, S=1024, D=256, H=16, DK=16
#define NB 16
#define NS 1024
#define ND 256
#define NH 16
#define NDK 16

// Projected tensors, head-contiguous [b][h][s][16].
// q stays fp32 (score accuracy); k,v stored fp16 (crossbar/DRAM halving).
__device__ float  g_q[NB * NS * ND];
__device__ __half g_kh[NB * NS * ND];
__device__ __half g_vh[NB * NS * ND];

// ---------------------------------------------------------------------------
// Packed dual-fp32 helpers (Blackwell f32x2).
// ---------------------------------------------------------------------------
typedef unsigned long long ull;

static __device__ __forceinline__ ull pack2(float lo, float hi) {
    ull r;
    asm("mov.b64 %0, {%1, %2};" : "=l"(r) : "f"(lo), "f"(hi));
    return r;
}
static __device__ __forceinline__ void unpack2(ull p, float& lo, float& hi) {
    asm("mov.b64 {%0, %1}, %2;" : "=f"(lo), "=f"(hi) : "l"(p));
}
static __device__ __forceinline__ ull fma2(ull a, ull b, ull c) {
    ull d;
    asm("fma.rn.f32x2 %0, %1, %2, %3;" : "=l"(d) : "l"(a), "l"(b), "l"(c));
    return d;
}
static __device__ __forceinline__ ull add2(ull a, ull b) {
    ull d;
    asm("add.rn.f32x2 %0, %1, %2;" : "=l"(d) : "l"(a), "l"(b));
    return d;
}
static __device__ __forceinline__ ull d2ll(double d) {
    return __double_as_longlong(d);
}
// half2 bits -> packed float pair
static __device__ __forceinline__ ull h2ll(unsigned int h2bits) {
    __half2 h = *reinterpret_cast<__half2*>(&h2bits);
    float2 f = __half22float2(h);
    return pack2(f.x, f.y);
}

// Fast exp on the fma/alu pipes (no MUFU). Input is already x*log2(e).
static __device__ __forceinline__ float fast_exp(float t) {
    float mm = t + 12582912.0f;             // round-to-nearest (magic 2^23+2^22)
    int   ik = __float_as_int(mm);
    float n  = mm - 12582912.0f;
    float f  = t - n;                        // f in [-0.5, 0.5]
    float f2 = f * f;
    float pA = fmaf(1.33335581464e-3f, f, 9.61812910763e-3f);
    float pB = fmaf(5.55041086648e-2f, f, 2.40226506959e-1f);
    float pC = fmaf(6.93147180560e-1f, f, 1.0f);
    float p  = fmaf(fmaf(pA, f2, pB), f2, pC);
    return __int_as_float(__float_as_int(p) + ((ik - 0x4B400000) << 23));
}

// ---------------------------------------------------------------------------
// Projection GEMM: C = X[16384,256] @ W[256,256] (+bias).
// z=0 -> g_q (fp32); z=1 -> g_kh (fp16); z=2 -> g_vh (fp16).
// Output layout head-contiguous [b][h][s][16].
// ---------------------------------------------------------------------------
__global__ __launch_bounds__(256, 2) void proj_kernel(
    const float* __restrict__ Qin, const float* __restrict__ Kin, const float* __restrict__ Vin,
    const float* __restrict__ Wq, const float* __restrict__ bq,
    const float* __restrict__ Wk, const float* __restrict__ Wv, const float* __restrict__ bv)
{
    __shared__ float As[128][17];
    __shared__ float Bs[16][128];

    const int z = blockIdx.z;
    const float* X    = (z == 0) ? Qin : ((z == 1) ? Kin : Vin);
    const float* W    = (z == 0) ? Wq  : ((z == 1) ? Wk  : Wv);
    const float* bias = (z == 0) ? bq  : ((z == 2) ? bv  : (const float*)0);

    const int m0 = blockIdx.y * 128;
    const int n0 = blockIdx.x * 128;
    const int tid = threadIdx.x;
    const int tx = tid & 15;
    const int ty = tid >> 4;

    ull accp[8][4];
#pragma unroll
    for (int i = 0; i < 8; i++)
#pragma unroll
        for (int j = 0; j < 4; j++) accp[i][j] = 0ULL;

    for (int kk = 0; kk < 256; kk += 16) {
#pragma unroll
        for (int i = 0; i < 8; i++) {
            int r = (tid >> 4) + i * 16;
            int c = tid & 15;
            As[r][c] = X[(size_t)(m0 + r) * 256 + kk + c];
        }
#pragma unroll
        for (int i = 0; i < 8; i++) {
            int kr = (tid >> 7) + i * 2;
            int n  = tid & 127;
            Bs[kr][n] = W[(size_t)(kk + kr) * 256 + n0 + n];
        }
        __syncthreads();

#pragma unroll
        for (int k = 0; k < 16; k++) {
            const double2* brow = (const double2*)&Bs[k][tx * 8];
            double2 b0 = brow[0], b1 = brow[1];
            ull bp[4] = { d2ll(b0.x), d2ll(b0.y), d2ll(b1.x), d2ll(b1.y) };
#pragma unroll
            for (int i = 0; i < 8; i++) {
                float a = As[ty * 8 + i][k];
                ull a2 = pack2(a, a);
#pragma unroll
                for (int j = 0; j < 4; j++)
                    accp[i][j] = fma2(a2, bp[j], accp[i][j]);
            }
        }
        __syncthreads();
    }

    float bj[8];
#pragma unroll
    for (int j = 0; j < 8; j++)
        bj[j] = bias ? bias[n0 + tx * 8 + j] : 0.f;

    const int hh  = (n0 + tx * 8) >> 4;    // head index
    const int dk0 = (tx * 8) & 15;         // 0 or 8 within head
#pragma unroll
    for (int i = 0; i < 8; i++) {
        int m = m0 + ty * 8 + i;
        int bb = m >> 10, s = m & 1023;
        float v[8];
#pragma unroll
        for (int j = 0; j < 4; j++) unpack2(accp[i][j], v[2 * j], v[2 * j + 1]);
#pragma unroll
        for (int j = 0; j < 8; j++) v[j] += bj[j];

        if (z == 0) {
            float* dst = &g_q[((size_t)(bb * NH + hh) * NS + s) * NDK + dk0];
            float4 o0 = make_float4(v[0], v[1], v[2], v[3]);
            float4 o1 = make_float4(v[4], v[5], v[6], v[7]);
            *(float4*)dst       = o0;
            *(float4*)(dst + 4) = o1;
        } else {
            __half2 h0 = __floats2half2_rn(v[0], v[1]);
            __half2 h1 = __floats2half2_rn(v[2], v[3]);
            __half2 h2 = __floats2half2_rn(v[4], v[5]);
            __half2 h3 = __floats2half2_rn(v[6], v[7]);
            uint4 o;
            o.x = *(unsigned int*)&h0; o.y = *(unsigned int*)&h1;
            o.z = *(unsigned int*)&h2; o.w = *(unsigned int*)&h3;
            __half* dst = (z == 1) ? &g_kh[((size_t)(bb * NH + hh) * NS + s) * NDK + dk0]
                                   : &g_vh[((size_t)(bb * NH + hh) * NS + s) * NDK + dk0];
            *(uint4*)dst = o;
        }
    }
}

// ---------------------------------------------------------------------------
// Fused attention, OCCUPANCY-2 variant. One block per (b, h, 16-row q tile),
// 256 threads = 8 warps, 2 CTAs/SM (smem ~104KB, regs <=128).
// Warp w: row group g=w&3 (rows 4g..4g+3), column half w>>2.
// kv tile: fp16, UNPADDED 32B rows, conflict-free via 1-bit XOR swizzle:
//   chunk c of row j lives at byte j*32 + ((c ^ ((j>>2)&1))*16).
// Score tile scq[g][j][4] fp32 (STS.128 / LDS.128). cpart overlaps dead msk.
// ---------------------------------------------------------------------------
#define SC_OFF    0         // 4 groups * 1024 * 4 = 16384 floats
#define KV_OFF    16384     // 1024*16 halves = 8192 float-equivalents
#define MSK_OFF   24576     // 1024 floats (cpart[512] reuses this after phase 1)
#define RSP_OFF   25600     // 32
#define RSUM_OFF  25632     // 16
#define QS_OFF    25648     // 256
#define ATTN_SMEM_FLOATS 25904
#define ATTN_SMEM_BYTES (ATTN_SMEM_FLOATS * 4)

// swizzled half-index of 16-byte chunk c (0/1) of kv row j
static __device__ __forceinline__ int kv_addr(int j, int c) {
    return j * 16 + ((c ^ ((j >> 2) & 1)) << 3);
}

__global__ __launch_bounds__(256, 2) void attn_kernel(
    const int* __restrict__ maskg, float* __restrict__ outg, float* __restrict__ attnw)
{
    extern __shared__ float sm[];
    float*  sc    = sm + SC_OFF;                 // scq[g][j][4]
    __half* kvh   = (__half*)(sm + KV_OFF);      // [1024][16] halves, swizzled
    float*  msk   = sm + MSK_OFF;
    float*  cpart = sm + MSK_OFF;                // overlaps msk (dead in phase 3)
    float*  rsp   = sm + RSP_OFF;
    float*  rsum  = sm + RSUM_OFF;
    float*  qs    = sm + QS_OFF;

    const int qt = blockIdx.x, h = blockIdx.y, b = blockIdx.z;
    const int tid   = threadIdx.x;
    const int lane  = tid & 31;
    const int w     = tid >> 5;        // 0..7
    const int g     = w & 3;           // row group (rows 4g..4g+3)
    const int rg    = g * 4;
    const int chalf = w >> 2;          // column half
    const int q0    = qt * 16;

    // --- stage q (16x16 fp32), mask, K half-tile (swizzled); ONE sync ---
    qs[tid] = g_q[((size_t)(b * NH + h) * NS + q0) * NDK + tid];
#pragma unroll
    for (int i = 0; i < 4; i++)
        msk[tid + i * 256] = (float)maskg[b * NS + tid + i * 256];
    {
        const uint4* kb = (const uint4*)(g_kh + (size_t)(b * NH + h) * NS * NDK);
#pragma unroll
        for (int i = 0; i < 8; i++) {
            int idx = tid + i * 256;          // 0..2047 16B-chunks
            int j = idx >> 1, c = idx & 1;
            *(uint4*)(kvh + kv_addr(j, c)) = kb[idx];
        }
    }
    __syncthreads();

    // q rows -> packed register pairs over d
    ull qp[4][8];
#pragma unroll
    for (int r = 0; r < 4; r++) {
        const double2* qrow = (const double2*)&qs[(rg + r) * 16];
#pragma unroll
        for (int c = 0; c < 4; c++) {
            double2 t = qrow[c];
            qp[r][2 * c]     = d2ll(t.x);
            qp[r][2 * c + 1] = d2ll(t.y);
        }
    }

    // --- Phase 1: scores; 2 swizzled LDS.128 of half K per column ---
    const float C_L2E4 = 0.36067376022224085f;   // log2(e)/4
    float rs[4] = {0.f, 0.f, 0.f, 0.f};
#pragma unroll 1
    for (int it = 0; it < 16; it++) {
        const int j = chalf * 512 + it * 32 + lane;
        uint4 ka  = *(const uint4*)(kvh + kv_addr(j, 0));
        uint4 kb4 = *(const uint4*)(kvh + kv_addr(j, 1));
        ull kp[8];
        kp[0] = h2ll(ka.x);  kp[1] = h2ll(ka.y);
        kp[2] = h2ll(ka.z);  kp[3] = h2ll(ka.w);
        kp[4] = h2ll(kb4.x); kp[5] = h2ll(kb4.y);
        kp[6] = h2ll(kb4.z); kp[7] = h2ll(kb4.w);
        const float m = msk[j];
        float ev[4];
#pragma unroll
        for (int r = 0; r < 4; r++) {
            ull sa = fma2(qp[r][0], kp[0], 0ULL);
            ull sb = fma2(qp[r][4], kp[4], 0ULL);
            sa = fma2(qp[r][1], kp[1], sa);
            sb = fma2(qp[r][5], kp[5], sb);
            sa = fma2(qp[r][2], kp[2], sa);
            sb = fma2(qp[r][6], kp[6], sb);
            sa = fma2(qp[r][3], kp[3], sa);
            sb = fma2(qp[r][7], kp[7], sb);
            ull s2 = add2(sa, sb);
            float slo, shi;
            unpack2(s2, slo, shi);
            ev[r] = fast_exp((slo + shi) * C_L2E4) * m;
            rs[r] += ev[r];
        }
        float4 e4;
        e4.x = ev[0]; e4.y = ev[1]; e4.z = ev[2]; e4.w = ev[3];
        *(float4*)&sc[(size_t)(g * 1024 + j) * 4] = e4;   // STS.128
    }
    // row-sum: lanes, then the two column halves
#pragma unroll
    for (int o = 16; o > 0; o >>= 1) {
#pragma unroll
        for (int r = 0; r < 4; r++)
            rs[r] += __shfl_xor_sync(0xffffffffu, rs[r], o);
    }
    if (lane == 0) {
#pragma unroll
        for (int r = 0; r < 4; r++) rsp[w * 4 + r] = rs[r];
    }
    __syncthreads();
    if (tid < 16) rsum[tid] = 1.0f / (rsp[tid] + rsp[tid + 16] + 1e-8f);
    __syncthreads();

    // --- stage V half-tile over kv (K no longer needed) ---
    {
        const uint4* vb = (const uint4*)(g_vh + (size_t)(b * NH + h) * NS * NDK);
#pragma unroll
        for (int i = 0; i < 8; i++) {
            int idx = tid + i * 256;
            int j = idx >> 1, c = idx & 1;
            *(uint4*)(kvh + kv_addr(j, c)) = vb[idx];
        }
    }
    __syncthreads();

    // --- Phase 3: context = sc @ v; attn_w (streaming) folded in ---
    float inv[4];
#pragma unroll
    for (int r = 0; r < 4; r++) inv[r] = rsum[rg + r];

    float* aw = attnw + ((size_t)(b * NH + h) * NS + q0) * NS;

    ull accp[4][8];
#pragma unroll
    for (int r = 0; r < 4; r++)
#pragma unroll
        for (int c = 0; c < 8; c++) accp[r][c] = 0ULL;

#pragma unroll 1
    for (int it = 0; it < 16; it++) {
        const int j = chalf * 512 + it * 32 + lane;
        uint4 va  = *(const uint4*)(kvh + kv_addr(j, 0));
        uint4 vb4 = *(const uint4*)(kvh + kv_addr(j, 1));
        ull vp[8];
        vp[0] = h2ll(va.x);  vp[1] = h2ll(va.y);
        vp[2] = h2ll(va.z);  vp[3] = h2ll(va.w);
        vp[4] = h2ll(vb4.x); vp[5] = h2ll(vb4.y);
        vp[6] = h2ll(vb4.z); vp[7] = h2ll(vb4.w);
        float4 e4 = *(const float4*)&sc[(size_t)(g * 1024 + j) * 4];  // LDS.128
        __stcs(aw + (size_t)(rg + 0) * NS + j, e4.x * inv[0]);
        __stcs(aw + (size_t)(rg + 1) * NS + j, e4.y * inv[1]);
        __stcs(aw + (size_t)(rg + 2) * NS + j, e4.z * inv[2]);
        __stcs(aw + (size_t)(rg + 3) * NS + j, e4.w * inv[3]);
        ull e0 = pack2(e4.x, e4.x), e1 = pack2(e4.y, e4.y);
        ull e2 = pack2(e4.z, e4.z), e3 = pack2(e4.w, e4.w);
#pragma unroll
        for (int c = 0; c < 8; c++) {
            accp[0][c] = fma2(e0, vp[c], accp[0][c]);
            accp[1][c] = fma2(e1, vp[c], accp[1][c]);
            accp[2][c] = fma2(e2, vp[c], accp[2][c]);
            accp[3][c] = fma2(e3, vp[c], accp[3][c]);
        }
    }

    // lane reduction on packed accumulators
#pragma unroll
    for (int o = 16; o > 0; o >>= 1)
#pragma unroll
        for (int r = 0; r < 4; r++)
#pragma unroll
            for (int c = 0; c < 8; c++)
                accp[r][c] = add2(accp[r][c], __shfl_xor_sync(0xffffffffu, accp[r][c], o));

    if (lane == 0) {
#pragma unroll
        for (int r = 0; r < 4; r++)
#pragma unroll
            for (int c = 0; c < 8; c++) {
                float lo, hi;
                unpack2(accp[r][c], lo, hi);
                cpart[w * 64 + r * 16 + 2 * c]     = lo;
                cpart[w * 64 + r * 16 + 2 * c + 1] = hi;
            }
    }
    __syncthreads();

    // combine the two column-half partials, normalize, write output
    {
        int r = tid >> 4, d = tid & 15;       // r in 0..15, d in 0..15
        int wg = r >> 2, rr = r & 3;
        float v = cpart[wg * 64 + rr * 16 + d] + cpart[(wg + 4) * 64 + rr * 16 + d];
        v *= rsum[r];
        outg[(size_t)(b * NS + q0 + r) * ND + h * NDK + d] = v;
    }
}

// ---------------------------------------------------------------------------
extern "C" void kernel_launch(void* const* d_in, const int* in_sizes, int n_in,
                              void* d_out, int out_size)
{
    const float* Qin  = (const float*)d_in[0];
    const float* Kin  = (const float*)d_in[1];
    const float* Vin  = (const float*)d_in[2];
    const int*   mask = (const int*)d_in[3];
    const float* Wq   = (const float*)d_in[4];
    const float* bq   = (const float*)d_in[5];
    const float* Wk   = (const float*)d_in[6];
    const float* Wv   = (const float*)d_in[7];
    const float* bv   = (const float*)d_in[8];

    float* out   = (float*)d_out;
    float* attnw = out + (size_t)NB * NS * ND;

    dim3 pg(2, 128, 3);
    proj_kernel<<<pg, 256>>>(Qin, Kin, Vin, Wq, bq, Wk, Wv, bv);

    cudaFuncSetAttribute(attn_kernel, cudaFuncAttributeMaxDynamicSharedMemorySize,
                         ATTN_SMEM_BYTES);
    dim3 ag(NS / 16, NH, NB);
    attn_kernel<<<ag, 256, ATTN_SMEM_BYTES>>>(mask, out, attnw);
}

// round 14
// speedup vs baseline: 1.5900x; 1.1444x over previous
#include <cuda_runtime.h>
#include <cuda_fp16.h>
#include <cstdint>

// Problem constants: B=16, S=1024, D=256, H=16, DK=16
#define NB 16
#define NS 1024
#define ND 256
#define NH 16
#define NDK 16

typedef unsigned int       u32;
typedef unsigned long long ull;

// Projected tensors, head-contiguous [b][h][s][16].
__device__ float  g_q[NB * NS * ND];
__device__ __half g_kh[NB * NS * ND];
__device__ __half g_vh[NB * NS * ND];

// ---------------------------------------------------------------------------
// Packed dual-fp32 helpers (Blackwell f32x2).
// ---------------------------------------------------------------------------
static __device__ __forceinline__ ull pack2(float lo, float hi) {
    ull r;
    asm("mov.b64 %0, {%1, %2};" : "=l"(r) : "f"(lo), "f"(hi));
    return r;
}
static __device__ __forceinline__ void unpack2(ull p, float& lo, float& hi) {
    asm("mov.b64 {%0, %1}, %2;" : "=f"(lo), "=f"(hi) : "l"(p));
}
static __device__ __forceinline__ ull fma2(ull a, ull b, ull c) {
    ull d;
    asm("fma.rn.f32x2 %0, %1, %2, %3;" : "=l"(d) : "l"(a), "l"(b), "l"(c));
    return d;
}
static __device__ __forceinline__ ull add2(ull a, ull b) {
    ull d;
    asm("add.rn.f32x2 %0, %1, %2;" : "=l"(d) : "l"(a), "l"(b));
    return d;
}
static __device__ __forceinline__ ull d2ll(double d) {
    return __double_as_longlong(d);
}
static __device__ __forceinline__ ull h2ll(u32 h2bits) {
    __half2 h = *reinterpret_cast<__half2*>(&h2bits);
    float2 f = __half22float2(h);
    return pack2(f.x, f.y);
}

// Fast exp on the fma/alu pipes (no MUFU). Input is already x*log2(e).
static __device__ __forceinline__ float fast_exp(float t) {
    float mm = t + 12582912.0f;
    int   ik = __float_as_int(mm);
    float n  = mm - 12582912.0f;
    float f  = t - n;
    float f2 = f * f;
    float pA = fmaf(1.33335581464e-3f, f, 9.61812910763e-3f);
    float pB = fmaf(5.55041086648e-2f, f, 2.40226506959e-1f);
    float pC = fmaf(6.93147180560e-1f, f, 1.0f);
    float p  = fmaf(fmaf(pA, f2, pB), f2, pC);
    return __int_as_float(__float_as_int(p) + ((ik - 0x4B400000) << 23));
}

// ---------------------------------------------------------------------------
// Tensor-core primitive wrappers.
// ---------------------------------------------------------------------------
static __device__ __forceinline__ void ldsm_x4(
    u32& r0, u32& r1, u32& r2, u32& r3, u32 addr)
{
    asm volatile("ldmatrix.sync.aligned.m8n8.x4.shared.b16 {%0, %1, %2, %3}, [%4];"
                 : "=r"(r0), "=r"(r1), "=r"(r2), "=r"(r3) : "r"(addr));
}
static __device__ __forceinline__ void ldsm_x2_trans(
    u32& r0, u32& r1, u32 addr)
{
    asm volatile("ldmatrix.sync.aligned.m8n8.x2.trans.shared.b16 {%0, %1}, [%2];"
                 : "=r"(r0), "=r"(r1) : "r"(addr));
}
static __device__ __forceinline__ void mma_16816(
    float& d0, float& d1, float& d2, float& d3,
    u32 fa0, u32 fa1, u32 fa2, u32 fa3,
    u32 fb0, u32 fb1)
{
    asm volatile("mma.sync.aligned.m16n8k16.row.col.f32.f16.f16.f32 "
                 "{%0, %1, %2, %3}, {%4, %5, %6, %7}, {%8, %9}, {%0, %1, %2, %3};"
                 : "+f"(d0), "+f"(d1), "+f"(d2), "+f"(d3)
                 : "r"(fa0), "r"(fa1), "r"(fa2), "r"(fa3), "r"(fb0), "r"(fb1));
}

// ---------------------------------------------------------------------------
// Projection GEMM (unchanged from R11).
// ---------------------------------------------------------------------------
__global__ __launch_bounds__(256, 2) void proj_kernel(
    const float* __restrict__ Qin, const float* __restrict__ Kin, const float* __restrict__ Vin,
    const float* __restrict__ Wq, const float* __restrict__ bq,
    const float* __restrict__ Wk, const float* __restrict__ Wv, const float* __restrict__ bv)
{
    __shared__ float As[128][17];
    __shared__ float Bs[16][128];

    const int z = blockIdx.z;
    const float* X    = (z == 0) ? Qin : ((z == 1) ? Kin : Vin);
    const float* W    = (z == 0) ? Wq  : ((z == 1) ? Wk  : Wv);
    const float* bias = (z == 0) ? bq  : ((z == 2) ? bv  : (const float*)0);

    const int m0 = blockIdx.y * 128;
    const int n0 = blockIdx.x * 128;
    const int tid = threadIdx.x;
    const int tx = tid & 15;
    const int ty = tid >> 4;

    ull accp[8][4];
#pragma unroll
    for (int i = 0; i < 8; i++)
#pragma unroll
        for (int j = 0; j < 4; j++) accp[i][j] = 0ULL;

    for (int kk = 0; kk < 256; kk += 16) {
#pragma unroll
        for (int i = 0; i < 8; i++) {
            int r = (tid >> 4) + i * 16;
            int c = tid & 15;
            As[r][c] = X[(size_t)(m0 + r) * 256 + kk + c];
        }
#pragma unroll
        for (int i = 0; i < 8; i++) {
            int kr = (tid >> 7) + i * 2;
            int n  = tid & 127;
            Bs[kr][n] = W[(size_t)(kk + kr) * 256 + n0 + n];
        }
        __syncthreads();

#pragma unroll
        for (int k = 0; k < 16; k++) {
            const double2* brow = (const double2*)&Bs[k][tx * 8];
            double2 w0 = brow[0], w1 = brow[1];
            ull bp[4] = { d2ll(w0.x), d2ll(w0.y), d2ll(w1.x), d2ll(w1.y) };
#pragma unroll
            for (int i = 0; i < 8; i++) {
                float a = As[ty * 8 + i][k];
                ull a2 = pack2(a, a);
#pragma unroll
                for (int j = 0; j < 4; j++)
                    accp[i][j] = fma2(a2, bp[j], accp[i][j]);
            }
        }
        __syncthreads();
    }

    float bj[8];
#pragma unroll
    for (int j = 0; j < 8; j++)
        bj[j] = bias ? bias[n0 + tx * 8 + j] : 0.f;

    const int hh  = (n0 + tx * 8) >> 4;
    const int dk0 = (tx * 8) & 15;
#pragma unroll
    for (int i = 0; i < 8; i++) {
        int m = m0 + ty * 8 + i;
        int bb = m >> 10, s = m & 1023;
        float v[8];
#pragma unroll
        for (int j = 0; j < 4; j++) unpack2(accp[i][j], v[2 * j], v[2 * j + 1]);
#pragma unroll
        for (int j = 0; j < 8; j++) v[j] += bj[j];

        if (z == 0) {
            float* dst = &g_q[((size_t)(bb * NH + hh) * NS + s) * NDK + dk0];
            *(float4*)dst       = make_float4(v[0], v[1], v[2], v[3]);
            *(float4*)(dst + 4) = make_float4(v[4], v[5], v[6], v[7]);
        } else {
            __half2 h0 = __floats2half2_rn(v[0], v[1]);
            __half2 h1 = __floats2half2_rn(v[2], v[3]);
            __half2 h2 = __floats2half2_rn(v[4], v[5]);
            __half2 h3 = __floats2half2_rn(v[6], v[7]);
            uint4 o;
            o.x = *(u32*)&h0; o.y = *(u32*)&h1;
            o.z = *(u32*)&h2; o.w = *(u32*)&h3;
            __half* dst = (z == 1) ? &g_kh[((size_t)(bb * NH + hh) * NS + s) * NDK + dk0]
                                   : &g_vh[((size_t)(bb * NH + hh) * NS + s) * NDK + dk0];
            *(uint4*)dst = o;
        }
    }
}

// ---------------------------------------------------------------------------
// Fused attention: scores fp32 f32x2 (proven), context via HMMA m16n8k16.
// One block per (b, h, 16-row q tile), 256 threads = 8 warps, 2 CTAs/SM.
// Phase 1: warp w: rows (w&3)*4.., column half w>>2; sc written fp16
//   row-major stride 1032 halves (+4 banks/row -> ldmatrix conflict-free).
// Phase 3: warp w: keys w*128..+127, 8 chunks of k16: ldmatrix A (scores),
//   2x ldmatrix.x2.trans B (V), 2x mma; attn_w stores come from the A-frags.
// ---------------------------------------------------------------------------
#define SC_STRIDE 1032
#define SC_OFF    0         // 16*1032 halves = 8256 floats
#define KVK_OFF   8256      // 8192 floats (1024x16 halves, swizzled)
#define KVV_OFF   16448     // 8192 floats
#define CM_OFF    24640     // 2048 floats: mask (phase1) / cpart (phase3)
#define RSP_OFF   26688     // 32
#define RSUM_OFF  26720     // 16
#define QS_OFF    26736     // 256
#define ATTN_SMEM_FLOATS 26992
#define ATTN_SMEM_BYTES (ATTN_SMEM_FLOATS * 4)

// swizzled half-index of 16-byte chunk c (0/1) of kv row j
static __device__ __forceinline__ int kv_addr(int j, int c) {
    return j * 16 + ((c ^ ((j >> 2) & 1)) << 3);
}

__global__ __launch_bounds__(256, 2) void attn_kernel(
    const int* __restrict__ maskg, float* __restrict__ outg, float* __restrict__ attnw)
{
    extern __shared__ float sm[];
    __half* sch   = (__half*)(sm + SC_OFF);      // [16][1032] halves
    __half* kvK   = (__half*)(sm + KVK_OFF);
    __half* kvV   = (__half*)(sm + KVV_OFF);
    float*  msk   = sm + CM_OFF;
    float*  cpart = sm + CM_OFF;                 // overlaps msk (dead by phase 3)
    float*  rsp   = sm + RSP_OFF;
    float*  rsum  = sm + RSUM_OFF;
    float*  qs    = sm + QS_OFF;

    const int qt = blockIdx.x, h = blockIdx.y, b = blockIdx.z;
    const int tid   = threadIdx.x;
    const int lane  = tid & 31;
    const int w     = tid >> 5;        // 0..7
    const int g     = w & 3;           // phase-1 row group (rows 4g..4g+3)
    const int rg    = g * 4;
    const int chalf = w >> 2;          // phase-1 column half
    const int q0    = qt * 16;

    // --- stage q (16x16 fp32), mask, K and V half-tiles; ONE sync ---
    qs[tid] = g_q[((size_t)(b * NH + h) * NS + q0) * NDK + tid];
#pragma unroll
    for (int i = 0; i < 4; i++)
        msk[tid + i * 256] = (float)maskg[b * NS + tid + i * 256];
    {
        const uint4* kb = (const uint4*)(g_kh + (size_t)(b * NH + h) * NS * NDK);
        const uint4* vb = (const uint4*)(g_vh + (size_t)(b * NH + h) * NS * NDK);
#pragma unroll
        for (int i = 0; i < 8; i++) {
            int idx = tid + i * 256;          // 0..2047 16B-chunks
            int j = idx >> 1, c = idx & 1;
            *(uint4*)(kvK + kv_addr(j, c)) = kb[idx];
            *(uint4*)(kvV + kv_addr(j, c)) = vb[idx];
        }
    }
    __syncthreads();

    // q rows -> packed register pairs over d
    ull qp[4][8];
#pragma unroll
    for (int r = 0; r < 4; r++) {
        const double2* qrow = (const double2*)&qs[(rg + r) * 16];
#pragma unroll
        for (int c = 0; c < 4; c++) {
            double2 t = qrow[c];
            qp[r][2 * c]     = d2ll(t.x);
            qp[r][2 * c + 1] = d2ll(t.y);
        }
    }

    // --- Phase 1: scores (fp32 math), written to sch as fp16 ---
    const float C_L2E4 = 0.36067376022224085f;   // log2(e)/4
    float rs[4] = {0.f, 0.f, 0.f, 0.f};
#pragma unroll 1
    for (int it = 0; it < 16; it++) {
        const int j = chalf * 512 + it * 32 + lane;
        uint4 ka  = *(const uint4*)(kvK + kv_addr(j, 0));
        uint4 kb4 = *(const uint4*)(kvK + kv_addr(j, 1));
        ull kp[8];
        kp[0] = h2ll(ka.x);  kp[1] = h2ll(ka.y);
        kp[2] = h2ll(ka.z);  kp[3] = h2ll(ka.w);
        kp[4] = h2ll(kb4.x); kp[5] = h2ll(kb4.y);
        kp[6] = h2ll(kb4.z); kp[7] = h2ll(kb4.w);
        const float m = msk[j];
#pragma unroll
        for (int r = 0; r < 4; r++) {
            ull sa = fma2(qp[r][0], kp[0], 0ULL);
            ull sb = fma2(qp[r][4], kp[4], 0ULL);
            sa = fma2(qp[r][1], kp[1], sa);
            sb = fma2(qp[r][5], kp[5], sb);
            sa = fma2(qp[r][2], kp[2], sa);
            sb = fma2(qp[r][6], kp[6], sb);
            sa = fma2(qp[r][3], kp[3], sa);
            sb = fma2(qp[r][7], kp[7], sb);
            ull s2 = add2(sa, sb);
            float slo, shi;
            unpack2(s2, slo, shi);
            float e = fast_exp((slo + shi) * C_L2E4) * m;
            rs[r] += e;
            sch[(rg + r) * SC_STRIDE + j] = __float2half(e);
        }
    }
    // row-sum: lanes, then the two column halves
#pragma unroll
    for (int o = 16; o > 0; o >>= 1) {
#pragma unroll
        for (int r = 0; r < 4; r++)
            rs[r] += __shfl_xor_sync(0xffffffffu, rs[r], o);
    }
    if (lane == 0) {
#pragma unroll
        for (int r = 0; r < 4; r++) rsp[w * 4 + r] = rs[r];
    }
    __syncthreads();
    if (tid < 16) rsum[tid] = 1.0f / (rsp[tid] + rsp[tid + 16] + 1e-8f);
    __syncthreads();

    // --- Phase 3: context via HMMA; attn_w stores from A-frags ---
    {
        const u32 smem_u32 = (u32)__cvta_generic_to_shared(sm);
        const u32 sc_base  = smem_u32 + SC_OFF * 4;
        const u32 vv_base  = smem_u32 + KVV_OFF * 4;

        const int rlo = lane >> 2;
        const float inv_lo = rsum[rlo];
        const float inv_hi = rsum[rlo + 8];
        float* aw = attnw + ((size_t)(b * NH + h) * NS + q0) * NS;

        // ldmatrix lane-address components
        const int mI    = lane >> 3;                       // which 8x8 mat
        const int arow  = (lane & 7) + ((mI & 1) << 3);    // sc row
        const int acolo = (mI >> 1) << 3;                  // sc col offset
        const int keyof = lane & 15;

        float ol0 = 0.f, ol1 = 0.f, ol2 = 0.f, ol3 = 0.f;  // out dims 0-7
        float oh0 = 0.f, oh1 = 0.f, oh2 = 0.f, oh3 = 0.f;  // out dims 8-15

#pragma unroll
        for (int ch = 0; ch < 8; ch++) {
            const int k0 = w * 128 + ch * 16;

            // A frag: scores 16x16 chunk
            u32 fa0, fa1, fa2, fa3;
            const u32 addrA = sc_base + (u32)(arow * SC_STRIDE + k0 + acolo) * 2;
            ldsm_x4(fa0, fa1, fa2, fa3, addrA);

            // attn_w: normalized scores, float2 streaming stores
            {
                const int col0 = k0 + 2 * (lane & 3);
                float2 t0 = __half22float2(*reinterpret_cast<__half2*>(&fa0));
                float2 t1 = __half22float2(*reinterpret_cast<__half2*>(&fa1));
                float2 t2 = __half22float2(*reinterpret_cast<__half2*>(&fa2));
                float2 t3 = __half22float2(*reinterpret_cast<__half2*>(&fa3));
                t0.x *= inv_lo; t0.y *= inv_lo;
                t1.x *= inv_hi; t1.y *= inv_hi;
                t2.x *= inv_lo; t2.y *= inv_lo;
                t3.x *= inv_hi; t3.y *= inv_hi;
                __stcs((float2*)(aw + (size_t)rlo * NS + col0), t0);
                __stcs((float2*)(aw + (size_t)(rlo + 8) * NS + col0), t1);
                __stcs((float2*)(aw + (size_t)rlo * NS + col0 + 8), t2);
                __stcs((float2*)(aw + (size_t)(rlo + 8) * NS + col0 + 8), t3);
            }

            // B frags: V chunk (k16 x d8 twice), from swizzled fp16 V tile
            const int key = k0 + keyof;
            u32 fb0, fb1, fb2, fb3;
            const u32 addrB0 = vv_base + (u32)kv_addr(key, 0) * 2;
            const u32 addrB1 = vv_base + (u32)kv_addr(key, 1) * 2;
            ldsm_x2_trans(fb0, fb1, addrB0);
            ldsm_x2_trans(fb2, fb3, addrB1);

            mma_16816(ol0, ol1, ol2, ol3, fa0, fa1, fa2, fa3, fb0, fb1);
            mma_16816(oh0, oh1, oh2, oh3, fa0, fa1, fa2, fa3, fb2, fb3);
        }

        // per-warp partial out -> cpart[w][16][16]
        const int cb = w * 256 + 2 * (lane & 3);
        *(float2*)&cpart[cb + rlo * 16]           = make_float2(ol0, ol1);
        *(float2*)&cpart[cb + (rlo + 8) * 16]     = make_float2(ol2, ol3);
        *(float2*)&cpart[cb + rlo * 16 + 8]       = make_float2(oh0, oh1);
        *(float2*)&cpart[cb + (rlo + 8) * 16 + 8] = make_float2(oh2, oh3);
    }
    __syncthreads();

    // combine 8 warps' partials, normalize, write output
    {
        int r = tid >> 4, d = tid & 15;
        float v = 0.f;
#pragma unroll
        for (int ww = 0; ww < 8; ww++) v += cpart[ww * 256 + r * 16 + d];
        v *= rsum[r];
        outg[(size_t)(b * NS + q0 + r) * ND + h * NDK + d] = v;
    }
}

// ---------------------------------------------------------------------------
extern "C" void kernel_launch(void* const* d_in, const int* in_sizes, int n_in,
                              void* d_out, int out_size)
{
    const float* Qin  = (const float*)d_in[0];
    const float* Kin  = (const float*)d_in[1];
    const float* Vin  = (const float*)d_in[2];
    const int*   mask = (const int*)d_in[3];
    const float* Wq   = (const float*)d_in[4];
    const float* bq   = (const float*)d_in[5];
    const float* Wk   = (const float*)d_in[6];
    const float* Wv   = (const float*)d_in[7];
    const float* bv   = (const float*)d_in[8];

    float* out   = (float*)d_out;
    float* attnw = out + (size_t)NB * NS * ND;

    dim3 pg(2, 128, 3);
    proj_kernel<<<pg, 256>>>(Qin, Kin, Vin, Wq, bq, Wk, Wv, bv);

    cudaFuncSetAttribute(attn_kernel, cudaFuncAttributeMaxDynamicSharedMemorySize,
                         ATTN_SMEM_BYTES);
    dim3 ag(NS / 16, NH, NB);
    attn_kernel<<<ag, 256, ATTN_SMEM_BYTES>>>(mask, out, attnw);
}

// round 15
// speedup vs baseline: 2.1603x; 1.3587x over previous
#include <cuda_runtime.h>
#include <cuda_fp16.h>
#include <cstdint>

// Problem constants: B=16, S=1024, D=256, H=16, DK=16
#define NB 16
#define NS 1024
#define ND 256
#define NH 16
#define NDK 16

typedef unsigned int       u32;
typedef unsigned long long ull;

// Projected tensors, head-contiguous [b][h][s][16], all fp16.
__device__ __half g_qh[NB * NS * ND];
__device__ __half g_kh[NB * NS * ND];
__device__ __half g_vh[NB * NS * ND];

// ---------------------------------------------------------------------------
// Packed dual-fp32 helpers (Blackwell f32x2) — used by the projection GEMM.
// ---------------------------------------------------------------------------
static __device__ __forceinline__ ull pack2(float lo, float hi) {
    ull r;
    asm("mov.b64 %0, {%1, %2};" : "=l"(r) : "f"(lo), "f"(hi));
    return r;
}
static __device__ __forceinline__ void unpack2(ull p, float& lo, float& hi) {
    asm("mov.b64 {%0, %1}, %2;" : "=f"(lo), "=f"(hi) : "l"(p));
}
static __device__ __forceinline__ ull fma2(ull a, ull b, ull c) {
    ull d;
    asm("fma.rn.f32x2 %0, %1, %2, %3;" : "=l"(d) : "l"(a), "l"(b), "l"(c));
    return d;
}
static __device__ __forceinline__ ull d2ll(double d) {
    return __double_as_longlong(d);
}

// Fast exp on the fma/alu pipes (no MUFU). Input is already x*log2(e).
static __device__ __forceinline__ float fast_exp(float t) {
    float mm = t + 12582912.0f;
    int   ik = __float_as_int(mm);
    float n  = mm - 12582912.0f;
    float f  = t - n;
    float f2 = f * f;
    float pA = fmaf(1.33335581464e-3f, f, 9.61812910763e-3f);
    float pB = fmaf(5.55041086648e-2f, f, 2.40226506959e-1f);
    float pC = fmaf(6.93147180560e-1f, f, 1.0f);
    float p  = fmaf(fmaf(pA, f2, pB), f2, pC);
    return __int_as_float(__float_as_int(p) + ((ik - 0x4B400000) << 23));
}

// ---------------------------------------------------------------------------
// Tensor-core primitive wrappers.
// ---------------------------------------------------------------------------
static __device__ __forceinline__ void ldsm_x4(
    u32& r0, u32& r1, u32& r2, u32& r3, u32 addr)
{
    asm volatile("ldmatrix.sync.aligned.m8n8.x4.shared.b16 {%0, %1, %2, %3}, [%4];"
                 : "=r"(r0), "=r"(r1), "=r"(r2), "=r"(r3) : "r"(addr));
}
static __device__ __forceinline__ void ldsm_x2(
    u32& r0, u32& r1, u32 addr)
{
    asm volatile("ldmatrix.sync.aligned.m8n8.x2.shared.b16 {%0, %1}, [%2];"
                 : "=r"(r0), "=r"(r1) : "r"(addr));
}
static __device__ __forceinline__ void ldsm_x2_trans(
    u32& r0, u32& r1, u32 addr)
{
    asm volatile("ldmatrix.sync.aligned.m8n8.x2.trans.shared.b16 {%0, %1}, [%2];"
                 : "=r"(r0), "=r"(r1) : "r"(addr));
}
static __device__ __forceinline__ void mma_16816(
    float& d0, float& d1, float& d2, float& d3,
    u32 fa0, u32 fa1, u32 fa2, u32 fa3,
    u32 fb0, u32 fb1)
{
    asm volatile("mma.sync.aligned.m16n8k16.row.col.f32.f16.f16.f32 "
                 "{%0, %1, %2, %3}, {%4, %5, %6, %7}, {%8, %9}, {%0, %1, %2, %3};"
                 : "+f"(d0), "+f"(d1), "+f"(d2), "+f"(d3)
                 : "r"(fa0), "r"(fa1), "r"(fa2), "r"(fa3), "r"(fb0), "r"(fb1));
}

// ---------------------------------------------------------------------------
// Projection GEMM: C = X[16384,256] @ W[256,256] (+bias), fp16 out,
// head-contiguous [b][h][s][16].
// ---------------------------------------------------------------------------
__global__ __launch_bounds__(256, 2) void proj_kernel(
    const float* __restrict__ Qin, const float* __restrict__ Kin, const float* __restrict__ Vin,
    const float* __restrict__ Wq, const float* __restrict__ bq,
    const float* __restrict__ Wk, const float* __restrict__ Wv, const float* __restrict__ bv)
{
    __shared__ float As[128][17];
    __shared__ float Bs[16][128];

    const int z = blockIdx.z;
    const float* X    = (z == 0) ? Qin : ((z == 1) ? Kin : Vin);
    const float* W    = (z == 0) ? Wq  : ((z == 1) ? Wk  : Wv);
    const float* bias = (z == 0) ? bq  : ((z == 2) ? bv  : (const float*)0);
    __half* C         = (z == 0) ? g_qh : ((z == 1) ? g_kh : g_vh);

    const int m0 = blockIdx.y * 128;
    const int n0 = blockIdx.x * 128;
    const int tid = threadIdx.x;
    const int tx = tid & 15;
    const int ty = tid >> 4;

    ull accp[8][4];
#pragma unroll
    for (int i = 0; i < 8; i++)
#pragma unroll
        for (int j = 0; j < 4; j++) accp[i][j] = 0ULL;

    for (int kk = 0; kk < 256; kk += 16) {
#pragma unroll
        for (int i = 0; i < 8; i++) {
            int r = (tid >> 4) + i * 16;
            int c = tid & 15;
            As[r][c] = X[(size_t)(m0 + r) * 256 + kk + c];
        }
#pragma unroll
        for (int i = 0; i < 8; i++) {
            int kr = (tid >> 7) + i * 2;
            int n  = tid & 127;
            Bs[kr][n] = W[(size_t)(kk + kr) * 256 + n0 + n];
        }
        __syncthreads();

#pragma unroll
        for (int k = 0; k < 16; k++) {
            const double2* brow = (const double2*)&Bs[k][tx * 8];
            double2 w0 = brow[0], w1 = brow[1];
            ull bp[4] = { d2ll(w0.x), d2ll(w0.y), d2ll(w1.x), d2ll(w1.y) };
#pragma unroll
            for (int i = 0; i < 8; i++) {
                float a = As[ty * 8 + i][k];
                ull a2 = pack2(a, a);
#pragma unroll
                for (int j = 0; j < 4; j++)
                    accp[i][j] = fma2(a2, bp[j], accp[i][j]);
            }
        }
        __syncthreads();
    }

    float bj[8];
#pragma unroll
    for (int j = 0; j < 8; j++)
        bj[j] = bias ? bias[n0 + tx * 8 + j] : 0.f;

    const int hh  = (n0 + tx * 8) >> 4;
    const int dk0 = (tx * 8) & 15;
#pragma unroll
    for (int i = 0; i < 8; i++) {
        int m = m0 + ty * 8 + i;
        int bb = m >> 10, s = m & 1023;
        float v[8];
#pragma unroll
        for (int j = 0; j < 4; j++) unpack2(accp[i][j], v[2 * j], v[2 * j + 1]);
#pragma unroll
        for (int j = 0; j < 8; j++) v[j] += bj[j];

        __half2 h0 = __floats2half2_rn(v[0], v[1]);
        __half2 h1 = __floats2half2_rn(v[2], v[3]);
        __half2 h2 = __floats2half2_rn(v[4], v[5]);
        __half2 h3 = __floats2half2_rn(v[6], v[7]);
        uint4 o;
        o.x = *(u32*)&h0; o.y = *(u32*)&h1;
        o.z = *(u32*)&h2; o.w = *(u32*)&h3;
        __half* dst = &C[((size_t)(bb * NH + hh) * NS + s) * NDK + dk0];
        *(uint4*)dst = o;
    }
}

// ---------------------------------------------------------------------------
// Fused attention, full-HMMA. One block per (b, h, 16-row q tile),
// 256 threads = 8 warps, 2 CTAs/SM.
// Phase 1 (QK^T): A = Q tile fp16 (one ldmatrix.x4/warp), per warp 16 chunks
//   of 8 keys: ldmatrix.x2 (non-trans; K is [key][d] = B col-major) + mma;
//   exp+mask on fp32 frags, half2 stores into sch, quad-reduced rowsums.
// Phase 3 (PV): as R14 — ldmatrix.x4 A (scores) + 2x ldmatrix.x2.trans B (V),
//   attn_w streaming stores from A-frags.
// ---------------------------------------------------------------------------
#define SC_STRIDE 1032
#define SC_OFF    0         // 16*1032 halves = 8256 floats
#define KVK_OFF   8256      // 8192 floats (1024x16 halves, swizzled)
#define KVV_OFF   16448     // 8192 floats
#define CM_OFF    24640     // 2048 floats: mask (phase1) / cpart (phase3)
#define RSP_OFF   26688     // 128
#define RSUM_OFF  26816     // 16
#define QSH_OFF   26832     // 128 floats = 256 halves (q tile fp16)
#define ATTN_SMEM_FLOATS 26960
#define ATTN_SMEM_BYTES (ATTN_SMEM_FLOATS * 4)

// swizzled half-index of 16-byte chunk c (0/1) of kv row j
static __device__ __forceinline__ int kv_addr(int j, int c) {
    return j * 16 + ((c ^ ((j >> 2) & 1)) << 3);
}

__global__ __launch_bounds__(256, 2) void attn_kernel(
    const int* __restrict__ maskg, float* __restrict__ outg, float* __restrict__ attnw)
{
    extern __shared__ float sm[];
    __half* sch   = (__half*)(sm + SC_OFF);      // [16][1032] halves
    __half* kvK   = (__half*)(sm + KVK_OFF);
    __half* kvV   = (__half*)(sm + KVV_OFF);
    float*  msk   = sm + CM_OFF;
    float*  cpart = sm + CM_OFF;                 // overlaps msk (dead by phase 3)
    float*  rsp   = sm + RSP_OFF;
    float*  rsum  = sm + RSUM_OFF;
    __half* qsh   = (__half*)(sm + QSH_OFF);

    const int qt = blockIdx.x, h = blockIdx.y, b = blockIdx.z;
    const int tid   = threadIdx.x;
    const int lane  = tid & 31;
    const int w     = tid >> 5;        // 0..7
    const int q0    = qt * 16;
    const int rlo   = lane >> 2;       // D-frag low row (0..7)

    // --- stage q (16x16 fp16, contiguous), mask, K and V tiles; ONE sync ---
    if (tid < 128)
        ((u32*)qsh)[tid] = ((const u32*)(g_qh + ((size_t)(b * NH + h) * NS + q0) * NDK))[tid];
#pragma unroll
    for (int i = 0; i < 4; i++)
        msk[tid + i * 256] = (float)maskg[b * NS + tid + i * 256];
    {
        const uint4* kb = (const uint4*)(g_kh + (size_t)(b * NH + h) * NS * NDK);
        const uint4* vb = (const uint4*)(g_vh + (size_t)(b * NH + h) * NS * NDK);
#pragma unroll
        for (int i = 0; i < 8; i++) {
            int idx = tid + i * 256;          // 0..2047 16B-chunks
            int j = idx >> 1, c = idx & 1;
            *(uint4*)(kvK + kv_addr(j, c)) = kb[idx];
            *(uint4*)(kvV + kv_addr(j, c)) = vb[idx];
        }
    }
    __syncthreads();

    const u32 smem_u32 = (u32)__cvta_generic_to_shared(sm);
    const u32 sc_base  = smem_u32 + SC_OFF * 4;
    const u32 kk_base  = smem_u32 + KVK_OFF * 4;
    const u32 vv_base  = smem_u32 + KVV_OFF * 4;
    const u32 qs_base  = smem_u32 + QSH_OFF * 4;

    // ldmatrix lane-address components (shared by A-frag loads)
    const int mI    = lane >> 3;
    const int arow  = (lane & 7) + ((mI & 1) << 3);
    const int acolo = (mI >> 1) << 3;

    // --- Phase 1: scores via HMMA ---
    const float C_L2E4 = 0.36067376022224085f;   // log2(e)/4
    {
        // A frag: Q tile (row stride 16 halves), loaded once
        u32 qa0, qa1, qa2, qa3;
        ldsm_x4(qa0, qa1, qa2, qa3, qs_base + (u32)(arow * 16 + acolo) * 2);

        float rs_lo = 0.f, rs_hi = 0.f;
#pragma unroll
        for (int ch = 0; ch < 16; ch++) {
            const int k0 = w * 128 + ch * 8;
            // B frag: K rows (key = n, d = k), non-trans ldmatrix
            u32 fb0, fb1;
            const int bkey = k0 + (lane & 7);
            const int bchk = (lane >> 3) & 1;
            ldsm_x2(fb0, fb1, kk_base + (u32)kv_addr(bkey, bchk) * 2);

            float d0 = 0.f, d1 = 0.f, d2 = 0.f, d3 = 0.f;
            mma_16816(d0, d1, d2, d3, qa0, qa1, qa2, qa3, fb0, fb1);

            const int col0 = k0 + 2 * (lane & 3);
            float2 m2 = *(const float2*)&msk[col0];
            d0 = fast_exp(d0 * C_L2E4) * m2.x;
            d1 = fast_exp(d1 * C_L2E4) * m2.y;
            d2 = fast_exp(d2 * C_L2E4) * m2.x;
            d3 = fast_exp(d3 * C_L2E4) * m2.y;
            rs_lo += d0 + d1;
            rs_hi += d2 + d3;

            __half2 hlo = __floats2half2_rn(d0, d1);
            __half2 hhi = __floats2half2_rn(d2, d3);
            *(__half2*)&sch[rlo * SC_STRIDE + col0]       = hlo;
            *(__half2*)&sch[(rlo + 8) * SC_STRIDE + col0] = hhi;
        }
        // quad reduction (lanes 4r..4r+3 hold row r's partial over this warp)
        rs_lo += __shfl_xor_sync(0xffffffffu, rs_lo, 1);
        rs_lo += __shfl_xor_sync(0xffffffffu, rs_lo, 2);
        rs_hi += __shfl_xor_sync(0xffffffffu, rs_hi, 1);
        rs_hi += __shfl_xor_sync(0xffffffffu, rs_hi, 2);
        if ((lane & 3) == 0) {
            rsp[rlo * 8 + w]       = rs_lo;
            rsp[(rlo + 8) * 8 + w] = rs_hi;
        }
    }
    __syncthreads();
    if (tid < 16) {
        float s = 0.f;
#pragma unroll
        for (int ww = 0; ww < 8; ww++) s += rsp[tid * 8 + ww];
        rsum[tid] = 1.0f / (s + 1e-8f);
    }
    __syncthreads();

    // --- Phase 3: context via HMMA; attn_w stores from A-frags ---
    {
        const float inv_lo = rsum[rlo];
        const float inv_hi = rsum[rlo + 8];
        float* aw = attnw + ((size_t)(b * NH + h) * NS + q0) * NS;

        const int keyof = lane & 15;

        float ol0 = 0.f, ol1 = 0.f, ol2 = 0.f, ol3 = 0.f;  // out dims 0-7
        float oh0 = 0.f, oh1 = 0.f, oh2 = 0.f, oh3 = 0.f;  // out dims 8-15

#pragma unroll
        for (int ch = 0; ch < 8; ch++) {
            const int k0 = w * 128 + ch * 16;

            // A frag: scores 16x16 chunk
            u32 fa0, fa1, fa2, fa3;
            ldsm_x4(fa0, fa1, fa2, fa3,
                    sc_base + (u32)(arow * SC_STRIDE + k0 + acolo) * 2);

            // attn_w: normalized scores, float2 streaming stores
            {
                const int col0 = k0 + 2 * (lane & 3);
                float2 t0 = __half22float2(*reinterpret_cast<__half2*>(&fa0));
                float2 t1 = __half22float2(*reinterpret_cast<__half2*>(&fa1));
                float2 t2 = __half22float2(*reinterpret_cast<__half2*>(&fa2));
                float2 t3 = __half22float2(*reinterpret_cast<__half2*>(&fa3));
                t0.x *= inv_lo; t0.y *= inv_lo;
                t1.x *= inv_hi; t1.y *= inv_hi;
                t2.x *= inv_lo; t2.y *= inv_lo;
                t3.x *= inv_hi; t3.y *= inv_hi;
                __stcs((float2*)(aw + (size_t)rlo * NS + col0), t0);
                __stcs((float2*)(aw + (size_t)(rlo + 8) * NS + col0), t1);
                __stcs((float2*)(aw + (size_t)rlo * NS + col0 + 8), t2);
                __stcs((float2*)(aw + (size_t)(rlo + 8) * NS + col0 + 8), t3);
            }

            // B frags: V chunk (k16 x d8 twice), from swizzled fp16 V tile
            const int key = k0 + keyof;
            u32 fb0, fb1, fb2, fb3;
            ldsm_x2_trans(fb0, fb1, vv_base + (u32)kv_addr(key, 0) * 2);
            ldsm_x2_trans(fb2, fb3, vv_base + (u32)kv_addr(key, 1) * 2);

            mma_16816(ol0, ol1, ol2, ol3, fa0, fa1, fa2, fa3, fb0, fb1);
            mma_16816(oh0, oh1, oh2, oh3, fa0, fa1, fa2, fa3, fb2, fb3);
        }

        // per-warp partial out -> cpart[w][16][16]
        const int cb = w * 256 + 2 * (lane & 3);
        *(float2*)&cpart[cb + rlo * 16]           = make_float2(ol0, ol1);
        *(float2*)&cpart[cb + (rlo + 8) * 16]     = make_float2(ol2, ol3);
        *(float2*)&cpart[cb + rlo * 16 + 8]       = make_float2(oh0, oh1);
        *(float2*)&cpart[cb + (rlo + 8) * 16 + 8] = make_float2(oh2, oh3);
    }
    __syncthreads();

    // combine 8 warps' partials, normalize, write output
    {
        int r = tid >> 4, d = tid & 15;
        float v = 0.f;
#pragma unroll
        for (int ww = 0; ww < 8; ww++) v += cpart[ww * 256 + r * 16 + d];
        v *= rsum[r];
        outg[(size_t)(b * NS + q0 + r) * ND + h * NDK + d] = v;
    }
}

// ---------------------------------------------------------------------------
extern "C" void kernel_launch(void* const* d_in, const int* in_sizes, int n_in,
                              void* d_out, int out_size)
{
    const float* Qin  = (const float*)d_in[0];
    const float* Kin  = (const float*)d_in[1];
    const float* Vin  = (const float*)d_in[2];
    const int*   mask = (const int*)d_in[3];
    const float* Wq   = (const float*)d_in[4];
    const float* bq   = (const float*)d_in[5];
    const float* Wk   = (const float*)d_in[6];
    const float* Wv   = (const float*)d_in[7];
    const float* bv   = (const float*)d_in[8];

    float* out   = (float*)d_out;
    float* attnw = out + (size_t)NB * NS * ND;

    dim3 pg(2, 128, 3);
    proj_kernel<<<pg, 256>>>(Qin, Kin, Vin, Wq, bq, Wk, Wv, bv);

    cudaFuncSetAttribute(attn_kernel, cudaFuncAttributeMaxDynamicSharedMemorySize,
                         ATTN_SMEM_BYTES);
    dim3 ag(NS / 16, NH, NB);
    attn_kernel<<<ag, 256, ATTN_SMEM_BYTES>>>(mask, out, attnw);
}

// round 16
// speedup vs baseline: 2.2459x; 1.0396x over previous
#include <cuda_runtime.h>
#include <cuda_fp16.h>
#include <cstdint>

// Problem constants: B=16, S=1024, D=256, H=16, DK=16
#define NB 16
#define NS 1024
#define ND 256
#define NH 16
#define NDK 16

typedef unsigned int       u32;
typedef unsigned long long ull;

// Projected tensors, head-contiguous [b][h][s][16], all fp16.
__device__ __half g_qh[NB * NS * ND];
__device__ __half g_kh[NB * NS * ND];
__device__ __half g_vh[NB * NS * ND];

// ---------------------------------------------------------------------------
// Packed dual-fp32 helpers (Blackwell f32x2) — used by the projection GEMM.
// ---------------------------------------------------------------------------
static __device__ __forceinline__ ull pack2(float lo, float hi) {
    ull r;
    asm("mov.b64 %0, {%1, %2};" : "=l"(r) : "f"(lo), "f"(hi));
    return r;
}
static __device__ __forceinline__ void unpack2(ull p, float& lo, float& hi) {
    asm("mov.b64 {%0, %1}, %2;" : "=f"(lo), "=f"(hi) : "l"(p));
}
static __device__ __forceinline__ ull fma2(ull a, ull b, ull c) {
    ull d;
    asm("fma.rn.f32x2 %0, %1, %2, %3;" : "=l"(d) : "l"(a), "l"(b), "l"(c));
    return d;
}
static __device__ __forceinline__ ull d2ll(double d) {
    return __double_as_longlong(d);
}

// Fast exp on the fma/alu pipes (no MUFU). Input is already x*log2(e).
static __device__ __forceinline__ float fast_exp(float t) {
    float mm = t + 12582912.0f;
    int   ik = __float_as_int(mm);
    float n  = mm - 12582912.0f;
    float f  = t - n;
    float f2 = f * f;
    float pA = fmaf(1.33335581464e-3f, f, 9.61812910763e-3f);
    float pB = fmaf(5.55041086648e-2f, f, 2.40226506959e-1f);
    float pC = fmaf(6.93147180560e-1f, f, 1.0f);
    float p  = fmaf(fmaf(pA, f2, pB), f2, pC);
    return __int_as_float(__float_as_int(p) + ((ik - 0x4B400000) << 23));
}

// ---------------------------------------------------------------------------
// Tensor-core primitive wrappers.
// ---------------------------------------------------------------------------
static __device__ __forceinline__ void ldsm_x4(
    u32& r0, u32& r1, u32& r2, u32& r3, u32 addr)
{
    asm volatile("ldmatrix.sync.aligned.m8n8.x4.shared.b16 {%0, %1, %2, %3}, [%4];"
                 : "=r"(r0), "=r"(r1), "=r"(r2), "=r"(r3) : "r"(addr));
}
static __device__ __forceinline__ void ldsm_x2(
    u32& r0, u32& r1, u32 addr)
{
    asm volatile("ldmatrix.sync.aligned.m8n8.x2.shared.b16 {%0, %1}, [%2];"
                 : "=r"(r0), "=r"(r1) : "r"(addr));
}
static __device__ __forceinline__ void ldsm_x2_trans(
    u32& r0, u32& r1, u32 addr)
{
    asm volatile("ldmatrix.sync.aligned.m8n8.x2.trans.shared.b16 {%0, %1}, [%2];"
                 : "=r"(r0), "=r"(r1) : "r"(addr));
}
static __device__ __forceinline__ void mma_16816(
    float& d0, float& d1, float& d2, float& d3,
    u32 fa0, u32 fa1, u32 fa2, u32 fa3,
    u32 fb0, u32 fb1)
{
    asm volatile("mma.sync.aligned.m16n8k16.row.col.f32.f16.f16.f32 "
                 "{%0, %1, %2, %3}, {%4, %5, %6, %7}, {%8, %9}, {%0, %1, %2, %3};"
                 : "+f"(d0), "+f"(d1), "+f"(d2), "+f"(d3)
                 : "r"(fa0), "r"(fa1), "r"(fa2), "r"(fa3), "r"(fb0), "r"(fb1));
}
static __device__ __forceinline__ void mma_16808(
    float& d0, float& d1, float& d2, float& d3,
    u32 fa0, u32 fa1, u32 fb0)
{
    asm volatile("mma.sync.aligned.m16n8k8.row.col.f32.f16.f16.f32 "
                 "{%0, %1, %2, %3}, {%4, %5}, {%6}, {%0, %1, %2, %3};"
                 : "+f"(d0), "+f"(d1), "+f"(d2), "+f"(d3)
                 : "r"(fa0), "r"(fa1), "r"(fb0));
}

// ---------------------------------------------------------------------------
// Projection GEMM: C = X[16384,256] @ W[256,256] (+bias), fp16 out,
// head-contiguous [b][h][s][16].
// ---------------------------------------------------------------------------
__global__ __launch_bounds__(256, 2) void proj_kernel(
    const float* __restrict__ Qin, const float* __restrict__ Kin, const float* __restrict__ Vin,
    const float* __restrict__ Wq, const float* __restrict__ bq,
    const float* __restrict__ Wk, const float* __restrict__ Wv, const float* __restrict__ bv)
{
    __shared__ float As[128][17];
    __shared__ float Bs[16][128];

    const int z = blockIdx.z;
    const float* X    = (z == 0) ? Qin : ((z == 1) ? Kin : Vin);
    const float* W    = (z == 0) ? Wq  : ((z == 1) ? Wk  : Wv);
    const float* bias = (z == 0) ? bq  : ((z == 2) ? bv  : (const float*)0);
    __half* C         = (z == 0) ? g_qh : ((z == 1) ? g_kh : g_vh);

    const int m0 = blockIdx.y * 128;
    const int n0 = blockIdx.x * 128;
    const int tid = threadIdx.x;
    const int tx = tid & 15;
    const int ty = tid >> 4;

    ull accp[8][4];
#pragma unroll
    for (int i = 0; i < 8; i++)
#pragma unroll
        for (int j = 0; j < 4; j++) accp[i][j] = 0ULL;

    for (int kk = 0; kk < 256; kk += 16) {
#pragma unroll
        for (int i = 0; i < 8; i++) {
            int r = (tid >> 4) + i * 16;
            int c = tid & 15;
            As[r][c] = X[(size_t)(m0 + r) * 256 + kk + c];
        }
#pragma unroll
        for (int i = 0; i < 8; i++) {
            int kr = (tid >> 7) + i * 2;
            int n  = tid & 127;
            Bs[kr][n] = W[(size_t)(kk + kr) * 256 + n0 + n];
        }
        __syncthreads();

#pragma unroll
        for (int k = 0; k < 16; k++) {
            const double2* brow = (const double2*)&Bs[k][tx * 8];
            double2 w0 = brow[0], w1 = brow[1];
            ull bp[4] = { d2ll(w0.x), d2ll(w0.y), d2ll(w1.x), d2ll(w1.y) };
#pragma unroll
            for (int i = 0; i < 8; i++) {
                float a = As[ty * 8 + i][k];
                ull a2 = pack2(a, a);
#pragma unroll
                for (int j = 0; j < 4; j++)
                    accp[i][j] = fma2(a2, bp[j], accp[i][j]);
            }
        }
        __syncthreads();
    }

    float bj[8];
#pragma unroll
    for (int j = 0; j < 8; j++)
        bj[j] = bias ? bias[n0 + tx * 8 + j] : 0.f;

    const int hh  = (n0 + tx * 8) >> 4;
    const int dk0 = (tx * 8) & 15;
#pragma unroll
    for (int i = 0; i < 8; i++) {
        int m = m0 + ty * 8 + i;
        int bb = m >> 10, s = m & 1023;
        float v[8];
#pragma unroll
        for (int j = 0; j < 4; j++) unpack2(accp[i][j], v[2 * j], v[2 * j + 1]);
#pragma unroll
        for (int j = 0; j < 8; j++) v[j] += bj[j];

        __half2 h0 = __floats2half2_rn(v[0], v[1]);
        __half2 h1 = __floats2half2_rn(v[2], v[3]);
        __half2 h2 = __floats2half2_rn(v[4], v[5]);
        __half2 h3 = __floats2half2_rn(v[6], v[7]);
        uint4 o;
        o.x = *(u32*)&h0; o.y = *(u32*)&h1;
        o.z = *(u32*)&h2; o.w = *(u32*)&h3;
        __half* dst = &C[((size_t)(bb * NH + hh) * NS + s) * NDK + dk0];
        *(uint4*)dst = o;
    }
}

// ---------------------------------------------------------------------------
// Fused attention, full-HMMA with REGISTER-RESIDENT score fragments.
// One block per (b, h, 16-row q tile), 256 threads = 8 warps, 2 CTAs/SM.
// Pass 1 (QK^T): per warp 16 chunks of 8 keys: ldsm_x2(K) + mma.m16n8k16;
//   exp+mask on fp32 D-frags -> e kept as half2 A-frags in registers (32 regs).
// Pass 2 (PV): per chunk: attn_w streaming stores from e-frags, one
//   ldsm_x2_trans(V) (both d-halves), 2x mma.m16n8k8 (D-frag layout == A-frag
//   of k8 mma, so no smem score tile at all).
// ---------------------------------------------------------------------------
#define KVK_OFF   0         // 8192 floats (1024x16 halves, swizzled)
#define KVV_OFF   8192      // 8192 floats
#define CM_OFF    16384     // 2048 floats: mask (pass1) / cpart (pass2)
#define RSP_OFF   18432     // 128
#define RSUM_OFF  18560     // 16
#define QSH_OFF   18576     // 128 floats = 256 halves (q tile fp16)
#define ATTN_SMEM_FLOATS 18704
#define ATTN_SMEM_BYTES (ATTN_SMEM_FLOATS * 4)

// swizzled half-index of 16-byte chunk c (0/1) of kv row j
static __device__ __forceinline__ int kv_addr(int j, int c) {
    return j * 16 + ((c ^ ((j >> 2) & 1)) << 3);
}

__global__ __launch_bounds__(256, 2) void attn_kernel(
    const int* __restrict__ maskg, float* __restrict__ outg, float* __restrict__ attnw)
{
    extern __shared__ float sm[];
    __half* kvK   = (__half*)(sm + KVK_OFF);
    __half* kvV   = (__half*)(sm + KVV_OFF);
    float*  msk   = sm + CM_OFF;
    float*  cpart = sm + CM_OFF;                 // overlaps msk (dead by pass 2)
    float*  rsp   = sm + RSP_OFF;
    float*  rsum  = sm + RSUM_OFF;
    __half* qsh   = (__half*)(sm + QSH_OFF);

    const int qt = blockIdx.x, h = blockIdx.y, b = blockIdx.z;
    const int tid   = threadIdx.x;
    const int lane  = tid & 31;
    const int w     = tid >> 5;        // 0..7
    const int q0    = qt * 16;
    const int rlo   = lane >> 2;       // frag low row (0..7)

    // --- stage q (16x16 fp16), mask, K and V tiles; ONE sync ---
    if (tid < 128)
        ((u32*)qsh)[tid] = ((const u32*)(g_qh + ((size_t)(b * NH + h) * NS + q0) * NDK))[tid];
#pragma unroll
    for (int i = 0; i < 4; i++)
        msk[tid + i * 256] = (float)maskg[b * NS + tid + i * 256];
    {
        const uint4* kb = (const uint4*)(g_kh + (size_t)(b * NH + h) * NS * NDK);
        const uint4* vb = (const uint4*)(g_vh + (size_t)(b * NH + h) * NS * NDK);
#pragma unroll
        for (int i = 0; i < 8; i++) {
            int idx = tid + i * 256;          // 0..2047 16B-chunks
            int j = idx >> 1, c = idx & 1;
            *(uint4*)(kvK + kv_addr(j, c)) = kb[idx];
            *(uint4*)(kvV + kv_addr(j, c)) = vb[idx];
        }
    }
    __syncthreads();

    const u32 smem_u32 = (u32)__cvta_generic_to_shared(sm);
    const u32 kk_base  = smem_u32 + KVK_OFF * 4;
    const u32 vv_base  = smem_u32 + KVV_OFF * 4;
    const u32 qs_base  = smem_u32 + QSH_OFF * 4;

    // ldmatrix lane-address components for the Q A-frag
    const int mI    = lane >> 3;
    const int arow  = (lane & 7) + ((mI & 1) << 3);
    const int acolo = (mI >> 1) << 3;

    // B-frag addressing for K (non-trans) and V (trans): same lane pattern
    const int bkey_of = lane & 7;
    const int bchk    = (lane >> 3) & 1;

    // e fragments: 16 chunks x {low-rows half2, high-rows half2}
    u32 ef0[16], ef1[16];

    // --- Pass 1: QK^T scores via HMMA; e stays in registers ---
    const float C_L2E4 = 0.36067376022224085f;   // log2(e)/4
    {
        u32 qa0, qa1, qa2, qa3;
        ldsm_x4(qa0, qa1, qa2, qa3, qs_base + (u32)(arow * 16 + acolo) * 2);

        float rs_lo = 0.f, rs_hi = 0.f;
#pragma unroll
        for (int ch = 0; ch < 16; ch++) {
            const int k0 = w * 128 + ch * 8;
            u32 fb0, fb1;
            ldsm_x2(fb0, fb1, kk_base + (u32)kv_addr(k0 + bkey_of, bchk) * 2);

            float d0 = 0.f, d1 = 0.f, d2 = 0.f, d3 = 0.f;
            mma_16816(d0, d1, d2, d3, qa0, qa1, qa2, qa3, fb0, fb1);

            const int col0 = k0 + 2 * (lane & 3);
            float2 m2 = *(const float2*)&msk[col0];
            d0 = fast_exp(d0 * C_L2E4) * m2.x;
            d1 = fast_exp(d1 * C_L2E4) * m2.y;
            d2 = fast_exp(d2 * C_L2E4) * m2.x;
            d3 = fast_exp(d3 * C_L2E4) * m2.y;
            rs_lo += d0 + d1;
            rs_hi += d2 + d3;

            __half2 hlo = __floats2half2_rn(d0, d1);
            __half2 hhi = __floats2half2_rn(d2, d3);
            ef0[ch] = *(u32*)&hlo;
            ef1[ch] = *(u32*)&hhi;
        }
        // quad reduction (lanes 4r..4r+3 hold row r's partial over this warp)
        rs_lo += __shfl_xor_sync(0xffffffffu, rs_lo, 1);
        rs_lo += __shfl_xor_sync(0xffffffffu, rs_lo, 2);
        rs_hi += __shfl_xor_sync(0xffffffffu, rs_hi, 1);
        rs_hi += __shfl_xor_sync(0xffffffffu, rs_hi, 2);
        if ((lane & 3) == 0) {
            rsp[rlo * 8 + w]       = rs_lo;
            rsp[(rlo + 8) * 8 + w] = rs_hi;
        }
    }
    __syncthreads();
    if (tid < 16) {
        float s = 0.f;
#pragma unroll
        for (int ww = 0; ww < 8; ww++) s += rsp[tid * 8 + ww];
        rsum[tid] = 1.0f / (s + 1e-8f);
    }
    __syncthreads();

    // --- Pass 2: attn_w stores + PV via mma.m16n8k8 from register e-frags ---
    {
        const float inv_lo = rsum[rlo];
        const float inv_hi = rsum[rlo + 8];
        float* aw = attnw + ((size_t)(b * NH + h) * NS + q0) * NS;

        float ol0 = 0.f, ol1 = 0.f, ol2 = 0.f, ol3 = 0.f;  // out dims 0-7
        float oh0 = 0.f, oh1 = 0.f, oh2 = 0.f, oh3 = 0.f;  // out dims 8-15

#pragma unroll
        for (int ch = 0; ch < 16; ch++) {
            const int k0 = w * 128 + ch * 8;

            // attn_w: normalized e from register frags, float2 streaming stores
            {
                const int col0 = k0 + 2 * (lane & 3);
                float2 tl = __half22float2(*reinterpret_cast<__half2*>(&ef0[ch]));
                float2 th = __half22float2(*reinterpret_cast<__half2*>(&ef1[ch]));
                tl.x *= inv_lo; tl.y *= inv_lo;
                th.x *= inv_hi; th.y *= inv_hi;
                __stcs((float2*)(aw + (size_t)rlo * NS + col0), tl);
                __stcs((float2*)(aw + (size_t)(rlo + 8) * NS + col0), th);
            }

            // V B-frag: one trans load covers both d-halves (k8 x d8 x2)
            u32 vb0, vb1;
            ldsm_x2_trans(vb0, vb1,
                          vv_base + (u32)kv_addr(k0 + bkey_of, bchk) * 2);

            mma_16808(ol0, ol1, ol2, ol3, ef0[ch], ef1[ch], vb0);
            mma_16808(oh0, oh1, oh2, oh3, ef0[ch], ef1[ch], vb1);
        }

        // per-warp partial out -> cpart[w][16][16]
        const int cb = w * 256 + 2 * (lane & 3);
        *(float2*)&cpart[cb + rlo * 16]           = make_float2(ol0, ol1);
        *(float2*)&cpart[cb + (rlo + 8) * 16]     = make_float2(ol2, ol3);
        *(float2*)&cpart[cb + rlo * 16 + 8]       = make_float2(oh0, oh1);
        *(float2*)&cpart[cb + (rlo + 8) * 16 + 8] = make_float2(oh2, oh3);
    }
    __syncthreads();

    // combine 8 warps' partials, normalize, write output
    {
        int r = tid >> 4, d = tid & 15;
        float v = 0.f;
#pragma unroll
        for (int ww = 0; ww < 8; ww++) v += cpart[ww * 256 + r * 16 + d];
        v *= rsum[r];
        outg[(size_t)(b * NS + q0 + r) * ND + h * NDK + d] = v;
    }
}

// ---------------------------------------------------------------------------
extern "C" void kernel_launch(void* const* d_in, const int* in_sizes, int n_in,
                              void* d_out, int out_size)
{
    const float* Qin  = (const float*)d_in[0];
    const float* Kin  = (const float*)d_in[1];
    const float* Vin  = (const float*)d_in[2];
    const int*   mask = (const int*)d_in[3];
    const float* Wq   = (const float*)d_in[4];
    const float* bq   = (const float*)d_in[5];
    const float* Wk   = (const float*)d_in[6];
    const float* Wv   = (const float*)d_in[7];
    const float* bv   = (const float*)d_in[8];

    float* out   = (float*)d_out;
    float* attnw = out + (size_t)NB * NS * ND;

    dim3 pg(2, 128, 3);
    proj_kernel<<<pg, 256>>>(Qin, Kin, Vin, Wq, bq, Wk, Wv, bv);

    cudaFuncSetAttribute(attn_kernel, cudaFuncAttributeMaxDynamicSharedMemorySize,
                         ATTN_SMEM_BYTES);
    dim3 ag(NS / 16, NH, NB);
    attn_kernel<<<ag, 256, ATTN_SMEM_BYTES>>>(mask, out, attnw);
}